// round 9
// baseline (speedup 1.0000x reference)
#include <cuda_runtime.h>
#include <math.h>

#define NN 10000
#define NE 160000
#define ET (NE + NN)          // edges + self loops
#define CAP 1024              // per-node shared-memory edge capacity (max real deg ~45)
#define NEG_SLOPE 0.2f

// Scratch buffer selectors (resolved in DEVICE code only; no host symbol addresses)
#define BUF_EXT (-1)
#define BUF_XL  0
#define BUF_XR  1
#define BUF_H1  2
#define BUF_H2  3
#define BUF_H3  4

// ---------------- scratch (static device globals: allocation-free) ----------
__device__ __align__(16) float g_xl[(size_t)NN * 1024];
__device__ __align__(16) float g_xr[(size_t)NN * 1024];
__device__ __align__(16) float g_h1[(size_t)NN * 1024];
__device__ __align__(16) float g_h2[(size_t)NN * 512];
__device__ __align__(16) float g_h3[(size_t)NN * 128];
__device__ int   g_cnt[NN];
__device__ int   g_rowptr[NN + 1];
__device__ int   g_cur[NN];
__device__ int   g_srcs[ET];
__device__ float g_efb[ET];   // fallback logits storage (deg > CAP; effectively never)
__device__ int   g_is64;      // 1 if edge_index is int64, 0 if int32

__device__ __forceinline__ float* scratch(int id) {
    switch (id) {
        case BUF_XL: return g_xl;
        case BUF_XR: return g_xr;
        case BUF_H1: return g_h1;
        case BUF_H2: return g_h2;
        case BUF_H3: return g_h3;
    }
    return nullptr;
}

// ---------------- dtype detection -------------------------------------------
// Reads the first NE 8-byte words: NE*8 bytes == int32 buffer size (2*NE*4),
// and < int64 buffer size (2*NE*8) — in-bounds under either dtype.
// If the data really is int64, every word is a node id in [0, NN).
// If it is int32, words fuse two ids: lo + hi*2^32, out of range whenever
// hi != 0 (certain over 160000 random ids).
__global__ void detect_dtype(const long long* __restrict__ ei) {
    __shared__ int bad;
    if (threadIdx.x == 0) bad = 0;
    __syncthreads();
    int lbad = 0;
    for (int i = threadIdx.x; i < NE; i += blockDim.x) {
        long long v = ei[i];
        if (v < 0 || v >= NN) lbad = 1;
    }
    if (lbad) bad = 1;
    __syncthreads();
    if (threadIdx.x == 0) g_is64 = bad ? 0 : 1;
}

__device__ __forceinline__ int edge_at(const void* ei, int idx) {
    return g_is64 ? (int)((const long long*)ei)[idx]
                  : ((const int*)ei)[idx];
}

// ---------------- zero counters (graph-safe; no memset on device globals) ---
__global__ void zero_counters() {
    int i = blockIdx.x * blockDim.x + threadIdx.x;
    if (i < NN) { g_cnt[i] = 0; g_cur[i] = 0; }
}

// ---------------- CSR build -------------------------------------------------
__global__ void count_kernel(const void* __restrict__ ei) {
    int e = blockIdx.x * blockDim.x + threadIdx.x;
    if (e >= ET) return;
    int dst = (e < NE) ? edge_at(ei, NE + e) : (e - NE);
    if ((unsigned)dst < NN) atomicAdd(&g_cnt[dst], 1);
}

__global__ void scan_kernel() {
    __shared__ int part[1024];
    int t = threadIdx.x;
    const int CH = (NN + 1023) / 1024;   // 10
    int base = t * CH;
    int s = 0;
    for (int k = 0; k < CH; k++) {
        int i = base + k;
        if (i < NN) s += g_cnt[i];
    }
    part[t] = s;
    __syncthreads();
    // Hillis-Steele inclusive scan
    for (int off = 1; off < 1024; off <<= 1) {
        int v = (t >= off) ? part[t - off] : 0;
        __syncthreads();
        part[t] += v;
        __syncthreads();
    }
    int run = (t == 0) ? 0 : part[t - 1];
    for (int k = 0; k < CH; k++) {
        int i = base + k;
        if (i < NN) { run += g_cnt[i]; g_rowptr[i + 1] = run; }
    }
    if (t == 0) g_rowptr[0] = 0;
}

__global__ void fill_kernel(const void* __restrict__ ei) {
    int e = blockIdx.x * blockDim.x + threadIdx.x;
    if (e >= ET) return;
    int src, dst;
    if (e < NE) { src = edge_at(ei, e); dst = edge_at(ei, NE + e); }
    else        { src = dst = e - NE; }
    if ((unsigned)src >= NN || (unsigned)dst >= NN) return;
    int pos = atomicAdd(&g_cur[dst], 1);
    g_srcs[g_rowptr[dst] + pos] = src;
}

// ---------------- SGEMM: C[M,N] = A[M,K] @ B[K,N] + bias[N] -----------------
// 128x128 block tile, 8x8 per thread, 256 threads, BK=8.
__global__ __launch_bounds__(256) void sgemm_bias(
    const float* __restrict__ Aext, int Asel,
    const float* __restrict__ B, const float* __restrict__ bias,
    float* __restrict__ Cext, int Csel,
    int M, int N, int K)
{
    const float* A = (Asel >= 0) ? scratch(Asel) : Aext;
    float*       C = (Csel >= 0) ? scratch(Csel) : Cext;

    __shared__ float As[8][128];
    __shared__ float Bs[8][128];
    int tid = threadIdx.x;
    int tx = tid & 15, ty = tid >> 4;
    int brow = blockIdx.y * 128, bcol = blockIdx.x * 128;

    float acc[8][8];
    #pragma unroll
    for (int i = 0; i < 8; i++)
        #pragma unroll
        for (int j = 0; j < 8; j++) acc[i][j] = 0.f;

    int arow  = tid >> 1;          // 0..127
    int acol4 = (tid & 1) * 4;     // 0 or 4
    int brl   = tid >> 5;          // 0..7
    int bcol4 = (tid & 31) * 4;    // 0..124

    for (int kt = 0; kt < K; kt += 8) {
        float4 av = make_float4(0.f, 0.f, 0.f, 0.f);
        if (brow + arow < M)
            av = *(const float4*)(A + (size_t)(brow + arow) * K + kt + acol4);
        As[acol4 + 0][arow] = av.x;
        As[acol4 + 1][arow] = av.y;
        As[acol4 + 2][arow] = av.z;
        As[acol4 + 3][arow] = av.w;

        float4 bv = make_float4(0.f, 0.f, 0.f, 0.f);
        if (bcol + bcol4 < N)
            bv = *(const float4*)(B + (size_t)(kt + brl) * N + bcol + bcol4);
        *(float4*)&Bs[brl][bcol4] = bv;
        __syncthreads();

        #pragma unroll
        for (int kk = 0; kk < 8; kk++) {
            float a[8], b[8];
            #pragma unroll
            for (int i = 0; i < 8; i++) a[i] = As[kk][ty * 8 + i];
            #pragma unroll
            for (int j = 0; j < 8; j++) b[j] = Bs[kk][tx * 8 + j];
            #pragma unroll
            for (int i = 0; i < 8; i++)
                #pragma unroll
                for (int j = 0; j < 8; j++) acc[i][j] += a[i] * b[j];
        }
        __syncthreads();
    }

    #pragma unroll
    for (int i = 0; i < 8; i++) {
        int r = brow + ty * 8 + i;
        if (r >= M) continue;
        #pragma unroll
        for (int j = 0; j < 8; j++) {
            int c = bcol + tx * 8 + j;
            if (c < N) C[(size_t)r * N + c] = acc[i][j] + bias[c];
        }
    }
}

// ---------------- fused GATv2 edge stage (one block per dst node) -----------
// logits + segment softmax + weighted aggregation + bias + relu
__global__ __launch_bounds__(256) void gat_node(
    const float* __restrict__ att, const float* __restrict__ bias,
    int outsel, int F)
{
    const float* xl = g_xl;
    const float* xr = g_xr;
    float* out = scratch(outsel);

    int v = blockIdx.x;
    int start = g_rowptr[v];
    int deg   = g_rowptr[v + 1] - start;
    int F4 = F >> 2;

    extern __shared__ float sh[];
    float* s_xr  = sh;                 // F (16B aligned)
    float* s_att = sh + F;             // F (16B aligned: F%4==0)
    float* s_e   = sh + 2 * F;         // CAP
    int*   s_src = (int*)(sh + 2 * F + CAP); // CAP
    __shared__ float red[32];
    __shared__ float s_bcast;

    int tid = threadIdx.x, bs = blockDim.x;
    int lane = tid & 31, wid = tid >> 5, nw = bs >> 5;

    {
        const float4* xr4  = (const float4*)(xr + (size_t)v * F);
        const float4* att4 = (const float4*)att;
        for (int f = tid; f < F4; f += bs) {
            ((float4*)s_xr)[f]  = xr4[f];
            ((float4*)s_att)[f] = att4[f];
        }
    }
    for (int j = tid; j < deg && j < CAP; j += bs) s_src[j] = g_srcs[start + j];
    __syncthreads();

    // --- logits: one warp per edge, float4 inner loop ---
    for (int j = wid; j < deg; j += nw) {
        int s = (j < CAP) ? s_src[j] : g_srcs[start + j];
        const float4* xl4 = (const float4*)(xl + (size_t)s * F);
        float acc = 0.f;
        for (int f = lane; f < F4; f += 32) {
            float4 a = xl4[f];
            float4 r = ((const float4*)s_xr)[f];
            float4 w = ((const float4*)s_att)[f];
            float m;
            m = a.x + r.x; m = (m > 0.f) ? m : m * NEG_SLOPE; acc += m * w.x;
            m = a.y + r.y; m = (m > 0.f) ? m : m * NEG_SLOPE; acc += m * w.y;
            m = a.z + r.z; m = (m > 0.f) ? m : m * NEG_SLOPE; acc += m * w.z;
            m = a.w + r.w; m = (m > 0.f) ? m : m * NEG_SLOPE; acc += m * w.w;
        }
        #pragma unroll
        for (int o = 16; o; o >>= 1) acc += __shfl_down_sync(0xffffffffu, acc, o);
        if (lane == 0) {
            if (j < CAP) s_e[j] = acc;
            else         g_efb[start + j] = acc;
        }
    }
    __syncthreads();

    // --- segment max ---
    float mx = -INFINITY;
    for (int j = tid; j < deg; j += bs)
        mx = fmaxf(mx, (j < CAP) ? s_e[j] : g_efb[start + j]);
    #pragma unroll
    for (int o = 16; o; o >>= 1) mx = fmaxf(mx, __shfl_down_sync(0xffffffffu, mx, o));
    if (lane == 0) red[wid] = mx;
    __syncthreads();
    if (wid == 0) {
        float m2 = (lane < nw) ? red[lane] : -INFINITY;
        #pragma unroll
        for (int o = 16; o; o >>= 1) m2 = fmaxf(m2, __shfl_down_sync(0xffffffffu, m2, o));
        if (lane == 0) s_bcast = m2;
    }
    __syncthreads();
    float M = s_bcast;

    // --- exp + segment sum ---
    float zs = 0.f;
    for (int j = tid; j < deg; j += bs) {
        float e  = (j < CAP) ? s_e[j] : g_efb[start + j];
        float ez = __expf(e - M);
        if (j < CAP) s_e[j] = ez; else g_efb[start + j] = ez;
        zs += ez;
    }
    #pragma unroll
    for (int o = 16; o; o >>= 1) zs += __shfl_down_sync(0xffffffffu, zs, o);
    if (lane == 0) red[wid] = zs;
    __syncthreads();
    if (wid == 0) {
        float z2 = (lane < nw) ? red[lane] : 0.f;
        #pragma unroll
        for (int o = 16; o; o >>= 1) z2 += __shfl_down_sync(0xffffffffu, z2, o);
        if (lane == 0) s_bcast = z2;
    }
    __syncthreads();
    float inv = 1.f / s_bcast;

    // --- weighted aggregation + bias + relu (float4) ---
    const float4* bias4 = (const float4*)bias;
    float4* out4 = (float4*)(out + (size_t)v * F);
    for (int f = tid; f < F4; f += bs) {
        float4 acc = make_float4(0.f, 0.f, 0.f, 0.f);
        for (int j = 0; j < deg; j++) {
            int s    = (j < CAP) ? s_src[j] : g_srcs[start + j];
            float ez = (j < CAP) ? s_e[j]   : g_efb[start + j];
            float4 xv = ((const float4*)(xl + (size_t)s * F))[f];
            acc.x += ez * xv.x;
            acc.y += ez * xv.y;
            acc.z += ez * xv.z;
            acc.w += ez * xv.w;
        }
        float4 bv = bias4[f];
        float4 o;
        o.x = fmaxf(acc.x * inv + bv.x, 0.f);
        o.y = fmaxf(acc.y * inv + bv.y, 0.f);
        o.z = fmaxf(acc.z * inv + bv.z, 0.f);
        o.w = fmaxf(acc.w * inv + bv.w, 0.f);
        out4[f] = o;
    }
}

// ---------------- host -------------------------------------------------------
// Kernel launches only: no symbol addresses, no memsets, no allocations.
extern "C" void kernel_launch(void* const* d_in, const int* in_sizes, int n_in,
                              void* d_out, int out_size) {
    (void)in_sizes; (void)n_in; (void)out_size;

    const float* x  = (const float*)d_in[0];
    const void*  ei = d_in[1];                 // int32 or int64, detected on device
    const float *Wl1 = (const float*)d_in[2],  *bl1 = (const float*)d_in[3];
    const float *Wr1 = (const float*)d_in[4],  *br1 = (const float*)d_in[5];
    const float *at1 = (const float*)d_in[6],  *b1  = (const float*)d_in[7];
    const float *Wl2 = (const float*)d_in[8],  *bl2 = (const float*)d_in[9];
    const float *Wr2 = (const float*)d_in[10], *br2 = (const float*)d_in[11];
    const float *at2 = (const float*)d_in[12], *b2  = (const float*)d_in[13];
    const float *Wl3 = (const float*)d_in[14], *bl3 = (const float*)d_in[15];
    const float *Wr3 = (const float*)d_in[16], *br3 = (const float*)d_in[17];
    const float *at3 = (const float*)d_in[18], *b3  = (const float*)d_in[19];
    const float *Wc  = (const float*)d_in[20], *bc  = (const float*)d_in[21];
    float* out = (float*)d_out;

    // dtype detect + CSR build
    detect_dtype<<<1, 256>>>((const long long*)ei);
    zero_counters<<<(NN + 255) / 256, 256>>>();
    count_kernel<<<(ET + 255) / 256, 256>>>(ei);
    scan_kernel<<<1, 1024>>>();
    fill_kernel<<<(ET + 255) / 256, 256>>>(ei);

    auto gemm = [&](const float* Aext, int Asel, const float* B,
                    const float* bias, float* Cext, int Csel,
                    int M, int N, int K) {
        dim3 grid((N + 127) / 128, (M + 127) / 128);
        sgemm_bias<<<grid, 256>>>(Aext, Asel, B, bias, Cext, Csel, M, N, K);
    };
    auto gat = [&](const float* ATT, const float* B, int outsel, int F) {
        size_t shmem = (size_t)(2 * F + CAP) * sizeof(float) + CAP * sizeof(int);
        gat_node<<<NN, 256, shmem>>>(ATT, B, outsel, F);
    };

    // layer 1: 128 -> 1024
    gemm(x, BUF_EXT, Wl1, bl1, nullptr, BUF_XL, NN, 1024, 128);
    gemm(x, BUF_EXT, Wr1, br1, nullptr, BUF_XR, NN, 1024, 128);
    gat(at1, b1, BUF_H1, 1024);
    // layer 2: 1024 -> 512
    gemm(nullptr, BUF_H1, Wl2, bl2, nullptr, BUF_XL, NN, 512, 1024);
    gemm(nullptr, BUF_H1, Wr2, br2, nullptr, BUF_XR, NN, 512, 1024);
    gat(at2, b2, BUF_H2, 512);
    // layer 3: 512 -> 128
    gemm(nullptr, BUF_H2, Wl3, bl3, nullptr, BUF_XL, NN, 128, 512);
    gemm(nullptr, BUF_H2, Wr3, br3, nullptr, BUF_XR, NN, 128, 512);
    gat(at3, b3, BUF_H3, 128);
    // classifier: 128 -> 64
    gemm(nullptr, BUF_H3, Wc, bc, out, BUF_EXT, NN, 64, 128);
}

// round 10
// speedup vs baseline: 1.1667x; 1.1667x over previous
#include <cuda_runtime.h>
#include <math.h>

#define NN 10000
#define NE 160000
#define ET (NE + NN)          // edges + self loops
#define CAP 1024              // per-node shared-memory edge capacity (max real deg ~45)
#define NEG_SLOPE 0.2f

// Scratch buffer selectors (resolved in DEVICE code only; no host symbol addresses)
#define BUF_EXT (-1)
#define BUF_XL  0
#define BUF_XR  1
#define BUF_H1  2
#define BUF_H2  3
#define BUF_H3  4

// ---------------- scratch (static device globals: allocation-free) ----------
__device__ __align__(16) float g_xl[(size_t)NN * 1024];
__device__ __align__(16) float g_xr[(size_t)NN * 1024];
__device__ __align__(16) float g_h1[(size_t)NN * 1024];
__device__ __align__(16) float g_h2[(size_t)NN * 512];
__device__ __align__(16) float g_h3[(size_t)NN * 128];
__device__ int   g_cnt[NN];
__device__ int   g_rowptr[NN + 1];
__device__ int   g_cur[NN];
__device__ int   g_srcs[ET];
__device__ float g_efb[ET];   // fallback logits storage (deg > CAP; effectively never)
__device__ int   g_is64;      // 1 if edge_index is int64, 0 if int32

__device__ __forceinline__ float* scratch(int id) {
    switch (id) {
        case BUF_XL: return g_xl;
        case BUF_XR: return g_xr;
        case BUF_H1: return g_h1;
        case BUF_H2: return g_h2;
        case BUF_H3: return g_h3;
    }
    return nullptr;
}

// ---------------- zero counters + init dtype flag ----------------------------
__global__ void zero_counters() {
    int i = blockIdx.x * blockDim.x + threadIdx.x;
    if (i < NN) { g_cnt[i] = 0; g_cur[i] = 0; }
    if (i == 0) g_is64 = 1;
}

// ---------------- dtype detection (multi-block, grid-stride) -----------------
// Reads the first NE 8-byte words: NE*8 bytes == int32 buffer size (2*NE*4),
// in-bounds under either dtype. int64 data => every word in [0, NN).
// int32 data => words fuse two ids (lo + hi*2^32), out of range whenever hi!=0.
__global__ void detect_dtype(const long long* __restrict__ ei) {
    bool bad = false;
    for (int i = blockIdx.x * blockDim.x + threadIdx.x; i < NE;
         i += gridDim.x * blockDim.x) {
        long long v = ei[i];
        if (v < 0 || v >= NN) bad = true;
    }
    if (bad) g_is64 = 0;    // racing same-value stores: benign
}

__device__ __forceinline__ int edge_at(const void* ei, int idx) {
    return g_is64 ? (int)((const long long*)ei)[idx]
                  : ((const int*)ei)[idx];
}

// ---------------- CSR build -------------------------------------------------
__global__ void count_kernel(const void* __restrict__ ei) {
    int e = blockIdx.x * blockDim.x + threadIdx.x;
    if (e >= ET) return;
    int dst = (e < NE) ? edge_at(ei, NE + e) : (e - NE);
    if ((unsigned)dst < NN) atomicAdd(&g_cnt[dst], 1);
}

__global__ void scan_kernel() {
    __shared__ int part[1024];
    int t = threadIdx.x;
    const int CH = (NN + 1023) / 1024;   // 10
    int base = t * CH;
    int s = 0;
    for (int k = 0; k < CH; k++) {
        int i = base + k;
        if (i < NN) s += g_cnt[i];
    }
    part[t] = s;
    __syncthreads();
    for (int off = 1; off < 1024; off <<= 1) {
        int v = (t >= off) ? part[t - off] : 0;
        __syncthreads();
        part[t] += v;
        __syncthreads();
    }
    int run = (t == 0) ? 0 : part[t - 1];
    for (int k = 0; k < CH; k++) {
        int i = base + k;
        if (i < NN) { run += g_cnt[i]; g_rowptr[i + 1] = run; }
    }
    if (t == 0) g_rowptr[0] = 0;
}

__global__ void fill_kernel(const void* __restrict__ ei) {
    int e = blockIdx.x * blockDim.x + threadIdx.x;
    if (e >= ET) return;
    int src, dst;
    if (e < NE) { src = edge_at(ei, e); dst = edge_at(ei, NE + e); }
    else        { src = dst = e - NE; }
    if ((unsigned)src >= NN || (unsigned)dst >= NN) return;
    int pos = atomicAdd(&g_cur[dst], 1);
    g_srcs[g_rowptr[dst] + pos] = src;
}

// ---------------- SGEMM: C[M,N] = A[M,K] @ B[K,N] + bias[N] -----------------
// BMxBN=BMx128 tile, BK=16, 256 threads, TMx8 per thread, double-buffered smem.
// K must be a multiple of 16 (holds: 128/512/1024). N multiple of 4.
template<int BM, int TM>
__global__ __launch_bounds__(256) void sgemm_bias_t(
    const float* __restrict__ Aext, int Asel,
    const float* __restrict__ B, const float* __restrict__ bias,
    float* __restrict__ Cext, int Csel,
    int M, int N, int K)
{
    const float* A = (Asel >= 0) ? scratch(Asel) : Aext;
    float*       C = (Csel >= 0) ? scratch(Csel) : Cext;

    __shared__ float As[2][16][BM];
    __shared__ float Bs[2][16][128];

    int tid = threadIdx.x;
    int tx = tid & 15, ty = tid >> 4;
    int brow = blockIdx.y * BM, bcol = blockIdx.x * 128;

    float acc[TM][8];
    #pragma unroll
    for (int i = 0; i < TM; i++)
        #pragma unroll
        for (int j = 0; j < 8; j++) acc[i][j] = 0.f;

    // A: BM*16/4 float4 total; 256 threads -> AR per thread, 64-row stride
    constexpr int AR = BM / 64;          // 2 for BM=128, 1 for BM=64
    int arow = tid >> 2;                 // 0..63
    int acol = (tid & 3) * 4;            // 0,4,8,12
    // B: 16*128/4 = 512 float4 -> 2 per thread
    int bkr = tid >> 5;                  // 0..7
    int bcl = (tid & 31) * 4;            // 0..124

    float4 aReg[AR], bReg[2];
    bool bok = (bcol + bcl) < N;

    auto gload = [&](int kt) {
        #pragma unroll
        for (int r = 0; r < AR; r++) {
            int row = brow + arow + r * 64;
            aReg[r] = (row < M)
                ? *(const float4*)(A + (size_t)row * K + kt + acol)
                : make_float4(0.f, 0.f, 0.f, 0.f);
        }
        #pragma unroll
        for (int r = 0; r < 2; r++) {
            int kr = kt + bkr + r * 8;
            bReg[r] = bok
                ? *(const float4*)(B + (size_t)kr * N + bcol + bcl)
                : make_float4(0.f, 0.f, 0.f, 0.f);
        }
    };
    auto sstore = [&](int p) {
        #pragma unroll
        for (int r = 0; r < AR; r++) {
            int row = arow + r * 64;
            As[p][acol + 0][row] = aReg[r].x;
            As[p][acol + 1][row] = aReg[r].y;
            As[p][acol + 2][row] = aReg[r].z;
            As[p][acol + 3][row] = aReg[r].w;
        }
        #pragma unroll
        for (int r = 0; r < 2; r++)
            *(float4*)&Bs[p][bkr + r * 8][bcl] = bReg[r];
    };

    int nk = K >> 4;
    gload(0);
    sstore(0);
    __syncthreads();

    for (int t = 0; t < nk; t++) {
        int p = t & 1;
        if (t + 1 < nk) gload((t + 1) << 4);

        #pragma unroll
        for (int kk = 0; kk < 16; kk++) {
            float a[TM], b[8];
            #pragma unroll
            for (int i = 0; i < TM; i++) a[i] = As[p][kk][ty * TM + i];
            #pragma unroll
            for (int j = 0; j < 8; j++)  b[j] = Bs[p][kk][tx * 8 + j];
            #pragma unroll
            for (int i = 0; i < TM; i++)
                #pragma unroll
                for (int j = 0; j < 8; j++) acc[i][j] += a[i] * b[j];
        }

        if (t + 1 < nk) {
            sstore(1 - p);
            __syncthreads();
        }
    }

    #pragma unroll
    for (int i = 0; i < TM; i++) {
        int r = brow + ty * TM + i;
        if (r >= M) continue;
        #pragma unroll
        for (int j = 0; j < 8; j++) {
            int c = bcol + tx * 8 + j;
            if (c < N) C[(size_t)r * N + c] = acc[i][j] + bias[c];
        }
    }
}

// ---------------- fused GATv2 edge stage (one block per dst node) -----------
__global__ __launch_bounds__(256) void gat_node(
    const float* __restrict__ att, const float* __restrict__ bias,
    int outsel, int F)
{
    const float* xl = g_xl;
    const float* xr = g_xr;
    float* out = scratch(outsel);

    int v = blockIdx.x;
    int start = g_rowptr[v];
    int deg   = g_rowptr[v + 1] - start;
    int F4 = F >> 2;

    extern __shared__ float sh[];
    float* s_xr  = sh;                 // F
    float* s_att = sh + F;             // F
    float* s_e   = sh + 2 * F;         // CAP
    int*   s_src = (int*)(sh + 2 * F + CAP); // CAP
    __shared__ float red[32];
    __shared__ float s_bcast;

    int tid = threadIdx.x, bs = blockDim.x;
    int lane = tid & 31, wid = tid >> 5, nw = bs >> 5;

    {
        const float4* xr4  = (const float4*)(xr + (size_t)v * F);
        const float4* att4 = (const float4*)att;
        for (int f = tid; f < F4; f += bs) {
            ((float4*)s_xr)[f]  = xr4[f];
            ((float4*)s_att)[f] = att4[f];
        }
    }
    for (int j = tid; j < deg && j < CAP; j += bs) s_src[j] = g_srcs[start + j];
    __syncthreads();

    // --- logits: one warp per edge, float4 inner loop ---
    for (int j = wid; j < deg; j += nw) {
        int s = (j < CAP) ? s_src[j] : g_srcs[start + j];
        const float4* xl4 = (const float4*)(xl + (size_t)s * F);
        float acc = 0.f;
        for (int f = lane; f < F4; f += 32) {
            float4 a = xl4[f];
            float4 r = ((const float4*)s_xr)[f];
            float4 w = ((const float4*)s_att)[f];
            float m;
            m = a.x + r.x; m = (m > 0.f) ? m : m * NEG_SLOPE; acc += m * w.x;
            m = a.y + r.y; m = (m > 0.f) ? m : m * NEG_SLOPE; acc += m * w.y;
            m = a.z + r.z; m = (m > 0.f) ? m : m * NEG_SLOPE; acc += m * w.z;
            m = a.w + r.w; m = (m > 0.f) ? m : m * NEG_SLOPE; acc += m * w.w;
        }
        #pragma unroll
        for (int o = 16; o; o >>= 1) acc += __shfl_down_sync(0xffffffffu, acc, o);
        if (lane == 0) {
            if (j < CAP) s_e[j] = acc;
            else         g_efb[start + j] = acc;
        }
    }
    __syncthreads();

    // --- segment max ---
    float mx = -INFINITY;
    for (int j = tid; j < deg; j += bs)
        mx = fmaxf(mx, (j < CAP) ? s_e[j] : g_efb[start + j]);
    #pragma unroll
    for (int o = 16; o; o >>= 1) mx = fmaxf(mx, __shfl_down_sync(0xffffffffu, mx, o));
    if (lane == 0) red[wid] = mx;
    __syncthreads();
    if (wid == 0) {
        float m2 = (lane < nw) ? red[lane] : -INFINITY;
        #pragma unroll
        for (int o = 16; o; o >>= 1) m2 = fmaxf(m2, __shfl_down_sync(0xffffffffu, m2, o));
        if (lane == 0) s_bcast = m2;
    }
    __syncthreads();
    float M = s_bcast;

    // --- exp + segment sum ---
    float zs = 0.f;
    for (int j = tid; j < deg; j += bs) {
        float e  = (j < CAP) ? s_e[j] : g_efb[start + j];
        float ez = __expf(e - M);
        if (j < CAP) s_e[j] = ez; else g_efb[start + j] = ez;
        zs += ez;
    }
    #pragma unroll
    for (int o = 16; o; o >>= 1) zs += __shfl_down_sync(0xffffffffu, zs, o);
    if (lane == 0) red[wid] = zs;
    __syncthreads();
    if (wid == 0) {
        float z2 = (lane < nw) ? red[lane] : 0.f;
        #pragma unroll
        for (int o = 16; o; o >>= 1) z2 += __shfl_down_sync(0xffffffffu, z2, o);
        if (lane == 0) s_bcast = z2;
    }
    __syncthreads();
    float inv = 1.f / s_bcast;

    // --- weighted aggregation + bias + relu (float4) ---
    const float4* bias4 = (const float4*)bias;
    float4* out4 = (float4*)(out + (size_t)v * F);
    for (int f = tid; f < F4; f += bs) {
        float4 acc = make_float4(0.f, 0.f, 0.f, 0.f);
        for (int j = 0; j < deg; j++) {
            int s    = (j < CAP) ? s_src[j] : g_srcs[start + j];
            float ez = (j < CAP) ? s_e[j]   : g_efb[start + j];
            float4 xv = ((const float4*)(xl + (size_t)s * F))[f];
            acc.x += ez * xv.x;
            acc.y += ez * xv.y;
            acc.z += ez * xv.z;
            acc.w += ez * xv.w;
        }
        float4 bv = bias4[f];
        float4 o;
        o.x = fmaxf(acc.x * inv + bv.x, 0.f);
        o.y = fmaxf(acc.y * inv + bv.y, 0.f);
        o.z = fmaxf(acc.z * inv + bv.z, 0.f);
        o.w = fmaxf(acc.w * inv + bv.w, 0.f);
        out4[f] = o;
    }
}

// ---------------- host -------------------------------------------------------
// Kernel launches only: no symbol addresses, no memsets, no allocations.
extern "C" void kernel_launch(void* const* d_in, const int* in_sizes, int n_in,
                              void* d_out, int out_size) {
    (void)in_sizes; (void)n_in; (void)out_size;

    const float* x  = (const float*)d_in[0];
    const void*  ei = d_in[1];                 // int32 or int64, detected on device
    const float *Wl1 = (const float*)d_in[2],  *bl1 = (const float*)d_in[3];
    const float *Wr1 = (const float*)d_in[4],  *br1 = (const float*)d_in[5];
    const float *at1 = (const float*)d_in[6],  *b1  = (const float*)d_in[7];
    const float *Wl2 = (const float*)d_in[8],  *bl2 = (const float*)d_in[9];
    const float *Wr2 = (const float*)d_in[10], *br2 = (const float*)d_in[11];
    const float *at2 = (const float*)d_in[12], *b2  = (const float*)d_in[13];
    const float *Wl3 = (const float*)d_in[14], *bl3 = (const float*)d_in[15];
    const float *Wr3 = (const float*)d_in[16], *br3 = (const float*)d_in[17];
    const float *at3 = (const float*)d_in[18], *b3  = (const float*)d_in[19];
    const float *Wc  = (const float*)d_in[20], *bc  = (const float*)d_in[21];
    float* out = (float*)d_out;

    // dtype detect + CSR build
    zero_counters<<<(NN + 255) / 256, 256>>>();
    detect_dtype<<<64, 256>>>((const long long*)ei);
    count_kernel<<<(ET + 255) / 256, 256>>>(ei);
    scan_kernel<<<1, 1024>>>();
    fill_kernel<<<(ET + 255) / 256, 256>>>(ei);

    auto gemm = [&](const float* Aext, int Asel, const float* B,
                    const float* bias, float* Cext, int Csel,
                    int M, int N, int K) {
        if (N >= 256) {
            dim3 grid((N + 127) / 128, (M + 127) / 128);
            sgemm_bias_t<128, 8><<<grid, 256>>>(Aext, Asel, B, bias, Cext, Csel, M, N, K);
        } else {
            dim3 grid((N + 127) / 128, (M + 63) / 64);
            sgemm_bias_t<64, 4><<<grid, 256>>>(Aext, Asel, B, bias, Cext, Csel, M, N, K);
        }
    };
    auto gat = [&](const float* ATT, const float* B, int outsel, int F) {
        size_t shmem = (size_t)(2 * F + CAP) * sizeof(float) + CAP * sizeof(int);
        gat_node<<<NN, 256, shmem>>>(ATT, B, outsel, F);
    };

    // layer 1: 128 -> 1024
    gemm(x, BUF_EXT, Wl1, bl1, nullptr, BUF_XL, NN, 1024, 128);
    gemm(x, BUF_EXT, Wr1, br1, nullptr, BUF_XR, NN, 1024, 128);
    gat(at1, b1, BUF_H1, 1024);
    // layer 2: 1024 -> 512
    gemm(nullptr, BUF_H1, Wl2, bl2, nullptr, BUF_XL, NN, 512, 1024);
    gemm(nullptr, BUF_H1, Wr2, br2, nullptr, BUF_XR, NN, 512, 1024);
    gat(at2, b2, BUF_H2, 512);
    // layer 3: 512 -> 128
    gemm(nullptr, BUF_H2, Wl3, bl3, nullptr, BUF_XL, NN, 128, 512);
    gemm(nullptr, BUF_H2, Wr3, br3, nullptr, BUF_XR, NN, 128, 512);
    gat(at3, b3, BUF_H3, 128);
    // classifier: 128 -> 64
    gemm(nullptr, BUF_H3, Wc, bc, out, BUF_EXT, NN, 64, 128);
}

// round 12
// speedup vs baseline: 1.2185x; 1.0444x over previous
#include <cuda_runtime.h>
#include <cuda_bf16.h>
#include <math.h>
#include <stdint.h>

#define NN 10000
#define NE 160000
#define ET (NE + NN)
#define CAP 1024
#define NEG_SLOPE 0.2f

#define BUF_EXT (-1)
#define BUF_XL  0
#define BUF_XR  1
#define BUF_H1  2
#define BUF_H2  3
#define BUF_H3  4

// ---------------- scratch ----------------------------------------------------
__device__ __align__(16) float g_xl[(size_t)NN * 1024];
__device__ __align__(16) float g_xr[(size_t)NN * 1024];
__device__ __align__(16) float g_h1[(size_t)NN * 1024];
__device__ __align__(16) float g_h2[(size_t)NN * 512];
__device__ __align__(16) float g_h3[(size_t)NN * 128];
__device__ int   g_cnt[NN];
__device__ int   g_rowptr[NN + 1];
__device__ int   g_cur[NN];
__device__ int   g_srcs[ET];
__device__ float g_efb[ET];
__device__ int   g_is64;

__device__ __forceinline__ float* scratch(int id) {
    switch (id) {
        case BUF_XL: return g_xl;
        case BUF_XR: return g_xr;
        case BUF_H1: return g_h1;
        case BUF_H2: return g_h2;
        case BUF_H3: return g_h3;
    }
    return nullptr;
}

// ---------------- bf16 split helpers -----------------------------------------
__device__ __forceinline__ uint32_t pack_hi2(float a, float b, float& la, float& lb) {
    __nv_bfloat16 ha = __float2bfloat16_rn(a), hb = __float2bfloat16_rn(b);
    la = a - __bfloat162float(ha);
    lb = b - __bfloat162float(hb);
    return ((uint32_t)__bfloat16_as_ushort(hb) << 16) | __bfloat16_as_ushort(ha);
}
__device__ __forceinline__ uint32_t pack2(float a, float b) {
    return ((uint32_t)__bfloat16_as_ushort(__float2bfloat16_rn(b)) << 16)
         | __bfloat16_as_ushort(__float2bfloat16_rn(a));
}

__device__ __forceinline__ void mma16816(float* c, const uint32_t* a, const uint32_t* b) {
    asm volatile(
        "mma.sync.aligned.m16n8k16.row.col.f32.bf16.bf16.f32 "
        "{%0,%1,%2,%3}, {%4,%5,%6,%7}, {%8,%9}, {%0,%1,%2,%3};"
        : "+f"(c[0]), "+f"(c[1]), "+f"(c[2]), "+f"(c[3])
        : "r"(a[0]), "r"(a[1]), "r"(a[2]), "r"(a[3]), "r"(b[0]), "r"(b[1]));
}

// ---------------- split-bf16 mma.sync GEMM -----------------------------------
// C[M,N] = A[M,K] @ B[K,N] + bias[N], fp32 in/out.
// CTA 128x128, 8 warps (2x4), warp tile 64x32 (4x4 m16n8k16 atoms), BK=32.
// Split: A=Ah+Al, B=Bh+Bl (bf16); D += Ah*Bh + Ah*Bl + Al*Bh.
#define AST 40   // smem row stride in bf16 elems (80B: conflict-free b32 frag loads)

__global__ __launch_bounds__(256) void mma_gemm(
    const float* __restrict__ Aext, int Asel,
    const float* __restrict__ B, const float* __restrict__ bias,
    float* __restrict__ Cext, int Csel,
    int M, int N, int K)
{
    const float* A = (Asel >= 0) ? scratch(Asel) : Aext;
    float*       C = (Csel >= 0) ? scratch(Csel) : Cext;

    __shared__ __align__(16) uint16_t sAh[128 * AST];
    __shared__ __align__(16) uint16_t sAl[128 * AST];
    __shared__ __align__(16) uint16_t sBh[128 * AST];
    __shared__ __align__(16) uint16_t sBl[128 * AST];

    int tid = threadIdx.x, lane = tid & 31, wid = tid >> 5;
    int wm = (wid & 1) * 64;            // warp M offset in tile
    int wn = (wid >> 1) * 32;           // warp N offset in tile
    int brow = blockIdx.y * 128, bcol = blockIdx.x * 128;

    float c[4][4][4];
    #pragma unroll
    for (int mi = 0; mi < 4; mi++)
        #pragma unroll
        for (int ni = 0; ni < 4; ni++)
            #pragma unroll
            for (int q = 0; q < 4; q++) c[mi][ni][q] = 0.f;

    // A conversion mapping: thread -> row, 16-wide k half
    int ar = tid >> 1;
    int ak = (tid & 1) * 16;
    bool aok = (brow + ar) < M;
    // B conversion mapping: thread -> 4 n cols, 1 k row (x4 iterations)
    int bn4 = (tid & 31) * 4;
    int bkr = tid >> 5;
    bool bok = (bcol + bn4) < N;

    int r = lane >> 2, cc = (lane & 3) * 2;   // fragment lane decomposition

    for (int kt = 0; kt < K; kt += 32) {
        // ---- convert A chunk [128 x 32] -> hi/lo bf16 smem ----
        {
            const float4* src = (const float4*)(A + (size_t)(brow + ar) * K + kt + ak);
            uint32_t* dh = (uint32_t*)(sAh + ar * AST + ak);
            uint32_t* dl = (uint32_t*)(sAl + ar * AST + ak);
            #pragma unroll
            for (int q = 0; q < 4; q++) {
                float4 v = aok ? src[q] : make_float4(0.f, 0.f, 0.f, 0.f);
                float lx, ly, lz, lw;
                uint32_t h0 = pack_hi2(v.x, v.y, lx, ly);
                uint32_t h1 = pack_hi2(v.z, v.w, lz, lw);
                dh[q * 2] = h0; dh[q * 2 + 1] = h1;
                dl[q * 2] = pack2(lx, ly); dl[q * 2 + 1] = pack2(lz, lw);
            }
        }
        // ---- convert B chunk: sB[n][k] = W[kt+k][bcol+n] ----
        {
            #pragma unroll
            for (int rr = 0; rr < 4; rr++) {
                int k = bkr + rr * 8;
                float4 w = bok
                    ? *(const float4*)(B + (size_t)(kt + k) * N + bcol + bn4)
                    : make_float4(0.f, 0.f, 0.f, 0.f);
                float vv[4] = {w.x, w.y, w.z, w.w};
                #pragma unroll
                for (int i = 0; i < 4; i++) {
                    int n = bn4 + i;
                    __nv_bfloat16 hi = __float2bfloat16_rn(vv[i]);
                    float lo = vv[i] - __bfloat162float(hi);
                    sBh[n * AST + k] = __bfloat16_as_ushort(hi);
                    sBl[n * AST + k] = __bfloat16_as_ushort(__float2bfloat16_rn(lo));
                }
            }
        }
        __syncthreads();

        // ---- 2 k-steps of 16 ----
        #pragma unroll
        for (int ks = 0; ks < 2; ks++) {
            int kb = ks * 16;
            uint32_t ah[4][4], al[4][4], bh[4][2], bl[4][2];
            #pragma unroll
            for (int mi = 0; mi < 4; mi++) {
                const uint16_t* ph = sAh + (wm + mi * 16 + r) * AST + kb + cc;
                const uint16_t* pl = sAl + (wm + mi * 16 + r) * AST + kb + cc;
                ah[mi][0] = *(const uint32_t*)ph;
                ah[mi][1] = *(const uint32_t*)(ph + 8 * AST);
                ah[mi][2] = *(const uint32_t*)(ph + 8);
                ah[mi][3] = *(const uint32_t*)(ph + 8 * AST + 8);
                al[mi][0] = *(const uint32_t*)pl;
                al[mi][1] = *(const uint32_t*)(pl + 8 * AST);
                al[mi][2] = *(const uint32_t*)(pl + 8);
                al[mi][3] = *(const uint32_t*)(pl + 8 * AST + 8);
            }
            #pragma unroll
            for (int ni = 0; ni < 4; ni++) {
                const uint16_t* ph = sBh + (wn + ni * 8 + r) * AST + kb + cc;
                const uint16_t* pl = sBl + (wn + ni * 8 + r) * AST + kb + cc;
                bh[ni][0] = *(const uint32_t*)ph;
                bh[ni][1] = *(const uint32_t*)(ph + 8);
                bl[ni][0] = *(const uint32_t*)pl;
                bl[ni][1] = *(const uint32_t*)(pl + 8);
            }
            #pragma unroll
            for (int mi = 0; mi < 4; mi++)
                #pragma unroll
                for (int ni = 0; ni < 4; ni++) {
                    mma16816(c[mi][ni], ah[mi], bh[ni]);
                    mma16816(c[mi][ni], ah[mi], bl[ni]);
                    mma16816(c[mi][ni], al[mi], bh[ni]);
                }
        }
        __syncthreads();
    }

    // ---- epilogue: c fragments + bias -> C ----
    int r0 = brow + wm + r;
    int c0 = bcol + wn + cc;
    #pragma unroll
    for (int mi = 0; mi < 4; mi++) {
        #pragma unroll
        for (int ni = 0; ni < 4; ni++) {
            int col = c0 + ni * 8;
            if (col >= N) continue;
            float bx = bias[col], by = bias[col + 1];
            int row0 = r0 + mi * 16;
            if (row0 < M) {
                float2 v = make_float2(c[mi][ni][0] + bx, c[mi][ni][1] + by);
                *(float2*)(C + (size_t)row0 * N + col) = v;
            }
            int row1 = row0 + 8;
            if (row1 < M) {
                float2 v = make_float2(c[mi][ni][2] + bx, c[mi][ni][3] + by);
                *(float2*)(C + (size_t)row1 * N + col) = v;
            }
        }
    }
}

// ---------------- zero counters + dtype flag ---------------------------------
__global__ void zero_counters() {
    int i = blockIdx.x * blockDim.x + threadIdx.x;
    if (i < NN) { g_cnt[i] = 0; g_cur[i] = 0; }
    if (i == 0) g_is64 = 1;
}

__global__ void detect_dtype(const long long* __restrict__ ei) {
    bool bad = false;
    for (int i = blockIdx.x * blockDim.x + threadIdx.x; i < NE;
         i += gridDim.x * blockDim.x) {
        long long v = ei[i];
        if (v < 0 || v >= NN) bad = true;
    }
    if (bad) g_is64 = 0;
}

__device__ __forceinline__ int edge_at(const void* ei, int idx) {
    return g_is64 ? (int)((const long long*)ei)[idx]
                  : ((const int*)ei)[idx];
}

// ---------------- CSR build --------------------------------------------------
__global__ void count_kernel(const void* __restrict__ ei) {
    int e = blockIdx.x * blockDim.x + threadIdx.x;
    if (e >= ET) return;
    int dst = (e < NE) ? edge_at(ei, NE + e) : (e - NE);
    if ((unsigned)dst < NN) atomicAdd(&g_cnt[dst], 1);
}

__global__ void scan_kernel() {
    __shared__ int part[1024];
    int t = threadIdx.x;
    const int CH = (NN + 1023) / 1024;
    int base = t * CH;
    int s = 0;
    for (int k = 0; k < CH; k++) {
        int i = base + k;
        if (i < NN) s += g_cnt[i];
    }
    part[t] = s;
    __syncthreads();
    for (int off = 1; off < 1024; off <<= 1) {
        int v = (t >= off) ? part[t - off] : 0;
        __syncthreads();
        part[t] += v;
        __syncthreads();
    }
    int run = (t == 0) ? 0 : part[t - 1];
    for (int k = 0; k < CH; k++) {
        int i = base + k;
        if (i < NN) { run += g_cnt[i]; g_rowptr[i + 1] = run; }
    }
    if (t == 0) g_rowptr[0] = 0;
}

__global__ void fill_kernel(const void* __restrict__ ei) {
    int e = blockIdx.x * blockDim.x + threadIdx.x;
    if (e >= ET) return;
    int src, dst;
    if (e < NE) { src = edge_at(ei, e); dst = edge_at(ei, NE + e); }
    else        { src = dst = e - NE; }
    if ((unsigned)src >= NN || (unsigned)dst >= NN) return;
    int pos = atomicAdd(&g_cur[dst], 1);
    g_srcs[g_rowptr[dst] + pos] = src;
}

// ---------------- fused GATv2 edge stage (unchanged, passing) ----------------
__global__ __launch_bounds__(256) void gat_node(
    const float* __restrict__ att, const float* __restrict__ bias,
    int outsel, int F)
{
    const float* xl = g_xl;
    const float* xr = g_xr;
    float* out = scratch(outsel);

    int v = blockIdx.x;
    int start = g_rowptr[v];
    int deg   = g_rowptr[v + 1] - start;
    int F4 = F >> 2;

    extern __shared__ float sh[];
    float* s_xr  = sh;
    float* s_att = sh + F;
    float* s_e   = sh + 2 * F;
    int*   s_src = (int*)(sh + 2 * F + CAP);
    __shared__ float red[32];
    __shared__ float s_bcast;

    int tid = threadIdx.x, bs = blockDim.x;
    int lane = tid & 31, wid = tid >> 5, nw = bs >> 5;

    {
        const float4* xr4  = (const float4*)(xr + (size_t)v * F);
        const float4* att4 = (const float4*)att;
        for (int f = tid; f < F4; f += bs) {
            ((float4*)s_xr)[f]  = xr4[f];
            ((float4*)s_att)[f] = att4[f];
        }
    }
    for (int j = tid; j < deg && j < CAP; j += bs) s_src[j] = g_srcs[start + j];
    __syncthreads();

    for (int j = wid; j < deg; j += nw) {
        int s = (j < CAP) ? s_src[j] : g_srcs[start + j];
        const float4* xl4 = (const float4*)(xl + (size_t)s * F);
        float acc = 0.f;
        for (int f = lane; f < F4; f += 32) {
            float4 a = xl4[f];
            float4 r = ((const float4*)s_xr)[f];
            float4 w = ((const float4*)s_att)[f];
            float m;
            m = a.x + r.x; m = (m > 0.f) ? m : m * NEG_SLOPE; acc += m * w.x;
            m = a.y + r.y; m = (m > 0.f) ? m : m * NEG_SLOPE; acc += m * w.y;
            m = a.z + r.z; m = (m > 0.f) ? m : m * NEG_SLOPE; acc += m * w.z;
            m = a.w + r.w; m = (m > 0.f) ? m : m * NEG_SLOPE; acc += m * w.w;
        }
        #pragma unroll
        for (int o = 16; o; o >>= 1) acc += __shfl_down_sync(0xffffffffu, acc, o);
        if (lane == 0) {
            if (j < CAP) s_e[j] = acc;
            else         g_efb[start + j] = acc;
        }
    }
    __syncthreads();

    float mx = -INFINITY;
    for (int j = tid; j < deg; j += bs)
        mx = fmaxf(mx, (j < CAP) ? s_e[j] : g_efb[start + j]);
    #pragma unroll
    for (int o = 16; o; o >>= 1) mx = fmaxf(mx, __shfl_down_sync(0xffffffffu, mx, o));
    if (lane == 0) red[wid] = mx;
    __syncthreads();
    if (wid == 0) {
        float m2 = (lane < nw) ? red[lane] : -INFINITY;
        #pragma unroll
        for (int o = 16; o; o >>= 1) m2 = fmaxf(m2, __shfl_down_sync(0xffffffffu, m2, o));
        if (lane == 0) s_bcast = m2;
    }
    __syncthreads();
    float M = s_bcast;

    float zs = 0.f;
    for (int j = tid; j < deg; j += bs) {
        float e  = (j < CAP) ? s_e[j] : g_efb[start + j];
        float ez = __expf(e - M);
        if (j < CAP) s_e[j] = ez; else g_efb[start + j] = ez;
        zs += ez;
    }
    #pragma unroll
    for (int o = 16; o; o >>= 1) zs += __shfl_down_sync(0xffffffffu, zs, o);
    if (lane == 0) red[wid] = zs;
    __syncthreads();
    if (wid == 0) {
        float z2 = (lane < nw) ? red[lane] : 0.f;
        #pragma unroll
        for (int o = 16; o; o >>= 1) z2 += __shfl_down_sync(0xffffffffu, z2, o);
        if (lane == 0) s_bcast = z2;
    }
    __syncthreads();
    float inv = 1.f / s_bcast;

    const float4* bias4 = (const float4*)bias;
    float4* out4 = (float4*)(out + (size_t)v * F);
    for (int f = tid; f < F4; f += bs) {
        float4 acc = make_float4(0.f, 0.f, 0.f, 0.f);
        for (int j = 0; j < deg; j++) {
            int s    = (j < CAP) ? s_src[j] : g_srcs[start + j];
            float ez = (j < CAP) ? s_e[j]   : g_efb[start + j];
            float4 xv = ((const float4*)(xl + (size_t)s * F))[f];
            acc.x += ez * xv.x;
            acc.y += ez * xv.y;
            acc.z += ez * xv.z;
            acc.w += ez * xv.w;
        }
        float4 bv = bias4[f];
        float4 o;
        o.x = fmaxf(acc.x * inv + bv.x, 0.f);
        o.y = fmaxf(acc.y * inv + bv.y, 0.f);
        o.z = fmaxf(acc.z * inv + bv.z, 0.f);
        o.w = fmaxf(acc.w * inv + bv.w, 0.f);
        out4[f] = o;
    }
}

// ---------------- host --------------------------------------------------------
extern "C" void kernel_launch(void* const* d_in, const int* in_sizes, int n_in,
                              void* d_out, int out_size) {
    (void)in_sizes; (void)n_in; (void)out_size;

    const float* x  = (const float*)d_in[0];
    const void*  ei = d_in[1];
    const float *Wl1 = (const float*)d_in[2],  *bl1 = (const float*)d_in[3];
    const float *Wr1 = (const float*)d_in[4],  *br1 = (const float*)d_in[5];
    const float *at1 = (const float*)d_in[6],  *b1  = (const float*)d_in[7];
    const float *Wl2 = (const float*)d_in[8],  *bl2 = (const float*)d_in[9];
    const float *Wr2 = (const float*)d_in[10], *br2 = (const float*)d_in[11];
    const float *at2 = (const float*)d_in[12], *b2  = (const float*)d_in[13];
    const float *Wl3 = (const float*)d_in[14], *bl3 = (const float*)d_in[15];
    const float *Wr3 = (const float*)d_in[16], *br3 = (const float*)d_in[17];
    const float *at3 = (const float*)d_in[18], *b3  = (const float*)d_in[19];
    const float *Wc  = (const float*)d_in[20], *bc  = (const float*)d_in[21];
    float* out = (float*)d_out;

    zero_counters<<<(NN + 255) / 256, 256>>>();
    detect_dtype<<<64, 256>>>((const long long*)ei);
    count_kernel<<<(ET + 255) / 256, 256>>>(ei);
    scan_kernel<<<1, 1024>>>();
    fill_kernel<<<(ET + 255) / 256, 256>>>(ei);

    auto gemm = [&](const float* Aext, int Asel, const float* B,
                    const float* bias, float* Cext, int Csel,
                    int M, int N, int K) {
        dim3 grid((N + 127) / 128, (M + 127) / 128);
        mma_gemm<<<grid, 256>>>(Aext, Asel, B, bias, Cext, Csel, M, N, K);
    };
    auto gat = [&](const float* ATT, const float* B, int outsel, int F) {
        size_t shmem = (size_t)(2 * F + CAP) * sizeof(float) + CAP * sizeof(int);
        gat_node<<<NN, 256, shmem>>>(ATT, B, outsel, F);
    };

    // layer 1: 128 -> 1024
    gemm(x, BUF_EXT, Wl1, bl1, nullptr, BUF_XL, NN, 1024, 128);
    gemm(x, BUF_EXT, Wr1, br1, nullptr, BUF_XR, NN, 1024, 128);
    gat(at1, b1, BUF_H1, 1024);
    // layer 2: 1024 -> 512
    gemm(nullptr, BUF_H1, Wl2, bl2, nullptr, BUF_XL, NN, 512, 1024);
    gemm(nullptr, BUF_H1, Wr2, br2, nullptr, BUF_XR, NN, 512, 1024);
    gat(at2, b2, BUF_H2, 512);
    // layer 3: 512 -> 128
    gemm(nullptr, BUF_H2, Wl3, bl3, nullptr, BUF_XL, NN, 128, 512);
    gemm(nullptr, BUF_H2, Wr3, br3, nullptr, BUF_XR, NN, 128, 512);
    gat(at3, b3, BUF_H3, 128);
    // classifier: 128 -> 64
    gemm(nullptr, BUF_H3, Wc, bc, out, BUF_EXT, NN, 64, 128);
}

// round 13
// speedup vs baseline: 1.5588x; 1.2792x over previous
#include <cuda_runtime.h>
#include <cuda_bf16.h>
#include <math.h>
#include <stdint.h>

#define NN 10000
#define NE 160000
#define ET (NE + NN)
#define CAP 1024
#define NEG_SLOPE 0.2f

#define BUF_EXT (-1)
#define BUF_XL  0
#define BUF_XR  1
#define BUF_H1  2
#define BUF_H2  3
#define BUF_H3  4

// ---------------- scratch ----------------------------------------------------
__device__ __align__(16) float g_xl[(size_t)NN * 1024];
__device__ __align__(16) float g_xr[(size_t)NN * 1024];
__device__ __align__(16) float g_h1[(size_t)NN * 1024];
__device__ __align__(16) float g_h2[(size_t)NN * 512];
__device__ __align__(16) float g_h3[(size_t)NN * 128];
__device__ __align__(16) __nv_bfloat16 g_ah[(size_t)NN * 1024];   // A hi
__device__ __align__(16) __nv_bfloat16 g_al[(size_t)NN * 1024];   // A lo
__device__ __align__(16) __nv_bfloat16 g_wh[2 * 1024 * 1024];     // Wt hi (2 mats)
__device__ __align__(16) __nv_bfloat16 g_wl[2 * 1024 * 1024];     // Wt lo
__device__ int   g_cnt[NN];
__device__ int   g_rowptr[NN + 1];
__device__ int   g_cur[NN];
__device__ int   g_srcs[ET];
__device__ float g_efb[ET];
__device__ int   g_is64;

__device__ __forceinline__ float* scratch(int id) {
    switch (id) {
        case BUF_XL: return g_xl;
        case BUF_XR: return g_xr;
        case BUF_H1: return g_h1;
        case BUF_H2: return g_h2;
        case BUF_H3: return g_h3;
    }
    return nullptr;
}

// ---------------- split preparation ------------------------------------------
__global__ void conv_split(const float* __restrict__ inext, int insel, int n) {
    const float* in = (insel >= 0) ? scratch(insel) : inext;
    for (int i = blockIdx.x * blockDim.x + threadIdx.x; i < n;
         i += gridDim.x * blockDim.x) {
        float v = in[i];
        __nv_bfloat16 h = __float2bfloat16_rn(v);
        g_ah[i] = h;
        g_al[i] = __float2bfloat16_rn(v - __bfloat162float(h));
    }
}

// W [K,N] fp32  ->  Wt hi/lo [N,K] bf16 at offset woff
__global__ void trans_split(const float* __restrict__ W, int K, int N, int woff) {
    __shared__ float t[32][33];
    int n0 = blockIdx.x * 32, k0 = blockIdx.y * 32;
    int tx = threadIdx.x & 31, ty = threadIdx.x >> 5;   // 32x8
    #pragma unroll
    for (int i = 0; i < 32; i += 8) {
        int k = k0 + ty + i, n = n0 + tx;
        t[ty + i][tx] = (k < K && n < N) ? W[(size_t)k * N + n] : 0.f;
    }
    __syncthreads();
    #pragma unroll
    for (int i = 0; i < 32; i += 8) {
        int n = n0 + ty + i, k = k0 + tx;
        if (n < N && k < K) {
            float v = t[tx][ty + i];
            __nv_bfloat16 h = __float2bfloat16_rn(v);
            size_t o = (size_t)woff + (size_t)n * K + k;
            g_wh[o] = h;
            g_wl[o] = __float2bfloat16_rn(v - __bfloat162float(h));
        }
    }
}

// ---------------- mma helpers -------------------------------------------------
__device__ __forceinline__ void mma16816(float* c, const uint32_t* a, const uint32_t* b) {
    asm volatile(
        "mma.sync.aligned.m16n8k16.row.col.f32.bf16.bf16.f32 "
        "{%0,%1,%2,%3}, {%4,%5,%6,%7}, {%8,%9}, {%0,%1,%2,%3};"
        : "+f"(c[0]), "+f"(c[1]), "+f"(c[2]), "+f"(c[3])
        : "r"(a[0]), "r"(a[1]), "r"(a[2]), "r"(a[3]), "r"(b[0]), "r"(b[1]));
}
__device__ __forceinline__ uint32_t smem_u32(const void* p) {
    uint32_t a;
    asm("{ .reg .u64 t; cvta.to.shared.u64 t, %1; cvt.u32.u64 %0, t; }"
        : "=r"(a) : "l"(p));
    return a;
}
__device__ __forceinline__ void cpa8(uint32_t s, const void* g) {
    asm volatile("cp.async.ca.shared.global [%0], [%1], 8;"
                 :: "r"(s), "l"(g) : "memory");
}
#define CP_COMMIT() asm volatile("cp.async.commit_group;" ::: "memory")
#define CP_WAIT(n)  asm volatile("cp.async.wait_group %0;" :: "n"(n) : "memory")

// ---------------- split-bf16 mma.sync GEMM, cp.async double-buffered ---------
// C[M,N] = A[M,K] @ W[K,N] + bias, A pre-split in g_ah/g_al [M,K],
// W pre-split transposed in g_wh/g_wl [N,K] at woff.
// CTA 128x128, 8 warps (2x4), warp 64x32 (4x4 atoms), BK=32, 2-stage pipeline.
#define AST 40                    // smem row stride (elems); 80B rows
#define TILE_B (128 * AST * 2)    // 10240 B per tile
#define STAGE_B (4 * TILE_B)      // 40960 B per stage
#define SMEM_GEMM (2 * STAGE_B)   // 81920 B

__global__ __launch_bounds__(256) void mma_gemm(
    int woff, const float* __restrict__ bias,
    float* __restrict__ Cext, int Csel,
    int M, int N, int K)
{
    float* C = (Csel >= 0) ? scratch(Csel) : Cext;
    extern __shared__ char smem[];
    uint32_t sb = smem_u32(smem);

    int tid = threadIdx.x, lane = tid & 31, wid = tid >> 5;
    int wm = (wid & 1) * 64, wn = (wid >> 1) * 32;
    int brow = blockIdx.y * 128, bcol = blockIdx.x * 128;

    float c[4][4][4];
    #pragma unroll
    for (int mi = 0; mi < 4; mi++)
        #pragma unroll
        for (int ni = 0; ni < 4; ni++)
            #pragma unroll
            for (int q = 0; q < 4; q++) c[mi][ni][q] = 0.f;

    // load mapping: row-in-tile = tid>>1 (0..127), k-half = (tid&1)*16
    int lr = tid >> 1;
    int lk = (tid & 1) * 16;
    bool aok = (brow + lr) < M;
    bool bok = (bcol + lr) < N;
    const __nv_bfloat16* pAh = g_ah + (size_t)(brow + lr) * K + lk;
    const __nv_bfloat16* pAl = g_al + (size_t)(brow + lr) * K + lk;
    const __nv_bfloat16* pBh = g_wh + (size_t)woff + (size_t)(bcol + lr) * K + lk;
    const __nv_bfloat16* pBl = g_wl + (size_t)woff + (size_t)(bcol + lr) * K + lk;
    uint32_t so = (uint32_t)(lr * AST + lk) * 2;   // 8B-aligned

    auto load_stage = [&](int st, int kt) {
        uint32_t s0 = sb + st * STAGE_B + so;
        if (aok) {
            #pragma unroll
            for (int q = 0; q < 4; q++) cpa8(s0 + q * 8, pAh + kt + q * 4);
            #pragma unroll
            for (int q = 0; q < 4; q++) cpa8(s0 + TILE_B + q * 8, pAl + kt + q * 4);
        } else {
            uint2 z = make_uint2(0u, 0u);
            char* d = smem + st * STAGE_B + so;
            #pragma unroll
            for (int q = 0; q < 4; q++) {
                *(uint2*)(d + q * 8) = z;
                *(uint2*)(d + TILE_B + q * 8) = z;
            }
        }
        if (bok) {
            #pragma unroll
            for (int q = 0; q < 4; q++) cpa8(s0 + 2 * TILE_B + q * 8, pBh + kt + q * 4);
            #pragma unroll
            for (int q = 0; q < 4; q++) cpa8(s0 + 3 * TILE_B + q * 8, pBl + kt + q * 4);
        } else {
            uint2 z = make_uint2(0u, 0u);
            char* d = smem + st * STAGE_B + so;
            #pragma unroll
            for (int q = 0; q < 4; q++) {
                *(uint2*)(d + 2 * TILE_B + q * 8) = z;
                *(uint2*)(d + 3 * TILE_B + q * 8) = z;
            }
        }
    };

    int r = lane >> 2, cc = (lane & 3) * 2;
    int nch = K >> 5;

    load_stage(0, 0);
    CP_COMMIT();

    for (int t = 0; t < nch; t++) {
        if (t + 1 < nch) {
            load_stage((t + 1) & 1, (t + 1) * 32);
            CP_COMMIT();
            CP_WAIT(1);
        } else {
            CP_WAIT(0);
        }
        __syncthreads();

        const char* stb = smem + (t & 1) * STAGE_B;
        const uint16_t* sAh = (const uint16_t*)(stb);
        const uint16_t* sAl = (const uint16_t*)(stb + TILE_B);
        const uint16_t* sBh = (const uint16_t*)(stb + 2 * TILE_B);
        const uint16_t* sBl = (const uint16_t*)(stb + 3 * TILE_B);

        #pragma unroll
        for (int ks = 0; ks < 2; ks++) {
            int kb = ks * 16;
            uint32_t ah[4][4], al[4][4], bh[4][2], bl[4][2];
            #pragma unroll
            for (int mi = 0; mi < 4; mi++) {
                const uint16_t* ph = sAh + (wm + mi * 16 + r) * AST + kb + cc;
                const uint16_t* pl = sAl + (wm + mi * 16 + r) * AST + kb + cc;
                ah[mi][0] = *(const uint32_t*)ph;
                ah[mi][1] = *(const uint32_t*)(ph + 8 * AST);
                ah[mi][2] = *(const uint32_t*)(ph + 8);
                ah[mi][3] = *(const uint32_t*)(ph + 8 * AST + 8);
                al[mi][0] = *(const uint32_t*)pl;
                al[mi][1] = *(const uint32_t*)(pl + 8 * AST);
                al[mi][2] = *(const uint32_t*)(pl + 8);
                al[mi][3] = *(const uint32_t*)(pl + 8 * AST + 8);
            }
            #pragma unroll
            for (int ni = 0; ni < 4; ni++) {
                const uint16_t* ph = sBh + (wn + ni * 8 + r) * AST + kb + cc;
                const uint16_t* pl = sBl + (wn + ni * 8 + r) * AST + kb + cc;
                bh[ni][0] = *(const uint32_t*)ph;
                bh[ni][1] = *(const uint32_t*)(ph + 8);
                bl[ni][0] = *(const uint32_t*)pl;
                bl[ni][1] = *(const uint32_t*)(pl + 8);
            }
            #pragma unroll
            for (int mi = 0; mi < 4; mi++)
                #pragma unroll
                for (int ni = 0; ni < 4; ni++) {
                    mma16816(c[mi][ni], ah[mi], bh[ni]);
                    mma16816(c[mi][ni], ah[mi], bl[ni]);
                    mma16816(c[mi][ni], al[mi], bh[ni]);
                }
        }
        __syncthreads();
    }

    // epilogue
    int r0 = brow + wm + r;
    int c0 = bcol + wn + cc;
    #pragma unroll
    for (int mi = 0; mi < 4; mi++) {
        #pragma unroll
        for (int ni = 0; ni < 4; ni++) {
            int col = c0 + ni * 8;
            if (col >= N) continue;
            float bx = bias[col], by = bias[col + 1];
            int row0 = r0 + mi * 16;
            if (row0 < M)
                *(float2*)(C + (size_t)row0 * N + col) =
                    make_float2(c[mi][ni][0] + bx, c[mi][ni][1] + by);
            int row1 = row0 + 8;
            if (row1 < M)
                *(float2*)(C + (size_t)row1 * N + col) =
                    make_float2(c[mi][ni][2] + bx, c[mi][ni][3] + by);
        }
    }
}

// ---------------- zero counters + dtype flag ---------------------------------
__global__ void zero_counters() {
    int i = blockIdx.x * blockDim.x + threadIdx.x;
    if (i < NN) { g_cnt[i] = 0; g_cur[i] = 0; }
    if (i == 0) g_is64 = 1;
}

__global__ void detect_dtype(const long long* __restrict__ ei) {
    bool bad = false;
    for (int i = blockIdx.x * blockDim.x + threadIdx.x; i < NE;
         i += gridDim.x * blockDim.x) {
        long long v = ei[i];
        if (v < 0 || v >= NN) bad = true;
    }
    if (bad) g_is64 = 0;
}

__device__ __forceinline__ int edge_at(const void* ei, int idx) {
    return g_is64 ? (int)((const long long*)ei)[idx]
                  : ((const int*)ei)[idx];
}

// ---------------- CSR build --------------------------------------------------
__global__ void count_kernel(const void* __restrict__ ei) {
    int e = blockIdx.x * blockDim.x + threadIdx.x;
    if (e >= ET) return;
    int dst = (e < NE) ? edge_at(ei, NE + e) : (e - NE);
    if ((unsigned)dst < NN) atomicAdd(&g_cnt[dst], 1);
}

__global__ void scan_kernel() {
    __shared__ int part[1024];
    int t = threadIdx.x;
    const int CH = (NN + 1023) / 1024;
    int base = t * CH;
    int s = 0;
    for (int k = 0; k < CH; k++) {
        int i = base + k;
        if (i < NN) s += g_cnt[i];
    }
    part[t] = s;
    __syncthreads();
    for (int off = 1; off < 1024; off <<= 1) {
        int v = (t >= off) ? part[t - off] : 0;
        __syncthreads();
        part[t] += v;
        __syncthreads();
    }
    int run = (t == 0) ? 0 : part[t - 1];
    for (int k = 0; k < CH; k++) {
        int i = base + k;
        if (i < NN) { run += g_cnt[i]; g_rowptr[i + 1] = run; }
    }
    if (t == 0) g_rowptr[0] = 0;
}

__global__ void fill_kernel(const void* __restrict__ ei) {
    int e = blockIdx.x * blockDim.x + threadIdx.x;
    if (e >= ET) return;
    int src, dst;
    if (e < NE) { src = edge_at(ei, e); dst = edge_at(ei, NE + e); }
    else        { src = dst = e - NE; }
    if ((unsigned)src >= NN || (unsigned)dst >= NN) return;
    int pos = atomicAdd(&g_cur[dst], 1);
    g_srcs[g_rowptr[dst] + pos] = src;
}

// ---------------- fused GATv2 edge stage (unchanged, passing) ----------------
__global__ __launch_bounds__(256) void gat_node(
    const float* __restrict__ att, const float* __restrict__ bias,
    int outsel, int F)
{
    const float* xl = g_xl;
    const float* xr = g_xr;
    float* out = scratch(outsel);

    int v = blockIdx.x;
    int start = g_rowptr[v];
    int deg   = g_rowptr[v + 1] - start;
    int F4 = F >> 2;

    extern __shared__ float sh[];
    float* s_xr  = sh;
    float* s_att = sh + F;
    float* s_e   = sh + 2 * F;
    int*   s_src = (int*)(sh + 2 * F + CAP);
    __shared__ float red[32];
    __shared__ float s_bcast;

    int tid = threadIdx.x, bs = blockDim.x;
    int lane = tid & 31, wid = tid >> 5, nw = bs >> 5;

    {
        const float4* xr4  = (const float4*)(xr + (size_t)v * F);
        const float4* att4 = (const float4*)att;
        for (int f = tid; f < F4; f += bs) {
            ((float4*)s_xr)[f]  = xr4[f];
            ((float4*)s_att)[f] = att4[f];
        }
    }
    for (int j = tid; j < deg && j < CAP; j += bs) s_src[j] = g_srcs[start + j];
    __syncthreads();

    for (int j = wid; j < deg; j += nw) {
        int s = (j < CAP) ? s_src[j] : g_srcs[start + j];
        const float4* xl4 = (const float4*)(xl + (size_t)s * F);
        float acc = 0.f;
        for (int f = lane; f < F4; f += 32) {
            float4 a = xl4[f];
            float4 r = ((const float4*)s_xr)[f];
            float4 w = ((const float4*)s_att)[f];
            float m;
            m = a.x + r.x; m = (m > 0.f) ? m : m * NEG_SLOPE; acc += m * w.x;
            m = a.y + r.y; m = (m > 0.f) ? m : m * NEG_SLOPE; acc += m * w.y;
            m = a.z + r.z; m = (m > 0.f) ? m : m * NEG_SLOPE; acc += m * w.z;
            m = a.w + r.w; m = (m > 0.f) ? m : m * NEG_SLOPE; acc += m * w.w;
        }
        #pragma unroll
        for (int o = 16; o; o >>= 1) acc += __shfl_down_sync(0xffffffffu, acc, o);
        if (lane == 0) {
            if (j < CAP) s_e[j] = acc;
            else         g_efb[start + j] = acc;
        }
    }
    __syncthreads();

    float mx = -INFINITY;
    for (int j = tid; j < deg; j += bs)
        mx = fmaxf(mx, (j < CAP) ? s_e[j] : g_efb[start + j]);
    #pragma unroll
    for (int o = 16; o; o >>= 1) mx = fmaxf(mx, __shfl_down_sync(0xffffffffu, mx, o));
    if (lane == 0) red[wid] = mx;
    __syncthreads();
    if (wid == 0) {
        float m2 = (lane < nw) ? red[lane] : -INFINITY;
        #pragma unroll
        for (int o = 16; o; o >>= 1) m2 = fmaxf(m2, __shfl_down_sync(0xffffffffu, m2, o));
        if (lane == 0) s_bcast = m2;
    }
    __syncthreads();
    float M = s_bcast;

    float zs = 0.f;
    for (int j = tid; j < deg; j += bs) {
        float e  = (j < CAP) ? s_e[j] : g_efb[start + j];
        float ez = __expf(e - M);
        if (j < CAP) s_e[j] = ez; else g_efb[start + j] = ez;
        zs += ez;
    }
    #pragma unroll
    for (int o = 16; o; o >>= 1) zs += __shfl_down_sync(0xffffffffu, zs, o);
    if (lane == 0) red[wid] = zs;
    __syncthreads();
    if (wid == 0) {
        float z2 = (lane < nw) ? red[lane] : 0.f;
        #pragma unroll
        for (int o = 16; o; o >>= 1) z2 += __shfl_down_sync(0xffffffffu, z2, o);
        if (lane == 0) s_bcast = z2;
    }
    __syncthreads();
    float inv = 1.f / s_bcast;

    const float4* bias4 = (const float4*)bias;
    float4* out4 = (float4*)(out + (size_t)v * F);
    for (int f = tid; f < F4; f += bs) {
        float4 acc = make_float4(0.f, 0.f, 0.f, 0.f);
        for (int j = 0; j < deg; j++) {
            int s    = (j < CAP) ? s_src[j] : g_srcs[start + j];
            float ez = (j < CAP) ? s_e[j]   : g_efb[start + j];
            float4 xv = ((const float4*)(xl + (size_t)s * F))[f];
            acc.x += ez * xv.x;
            acc.y += ez * xv.y;
            acc.z += ez * xv.z;
            acc.w += ez * xv.w;
        }
        float4 bv = bias4[f];
        float4 o;
        o.x = fmaxf(acc.x * inv + bv.x, 0.f);
        o.y = fmaxf(acc.y * inv + bv.y, 0.f);
        o.z = fmaxf(acc.z * inv + bv.z, 0.f);
        o.w = fmaxf(acc.w * inv + bv.w, 0.f);
        out4[f] = o;
    }
}

// ---------------- host --------------------------------------------------------
extern "C" void kernel_launch(void* const* d_in, const int* in_sizes, int n_in,
                              void* d_out, int out_size) {
    (void)in_sizes; (void)n_in; (void)out_size;

    const float* x  = (const float*)d_in[0];
    const void*  ei = d_in[1];
    const float *Wl1 = (const float*)d_in[2],  *bl1 = (const float*)d_in[3];
    const float *Wr1 = (const float*)d_in[4],  *br1 = (const float*)d_in[5];
    const float *at1 = (const float*)d_in[6],  *b1  = (const float*)d_in[7];
    const float *Wl2 = (const float*)d_in[8],  *bl2 = (const float*)d_in[9];
    const float *Wr2 = (const float*)d_in[10], *br2 = (const float*)d_in[11];
    const float *at2 = (const float*)d_in[12], *b2  = (const float*)d_in[13];
    const float *Wl3 = (const float*)d_in[14], *bl3 = (const float*)d_in[15];
    const float *Wr3 = (const float*)d_in[16], *br3 = (const float*)d_in[17];
    const float *at3 = (const float*)d_in[18], *b3  = (const float*)d_in[19];
    const float *Wc  = (const float*)d_in[20], *bc  = (const float*)d_in[21];
    float* out = (float*)d_out;

    cudaFuncSetAttribute(mma_gemm,
                         cudaFuncAttributeMaxDynamicSharedMemorySize, SMEM_GEMM);

    zero_counters<<<(NN + 255) / 256, 256>>>();
    detect_dtype<<<64, 256>>>((const long long*)ei);
    count_kernel<<<(ET + 255) / 256, 256>>>(ei);
    scan_kernel<<<1, 1024>>>();
    fill_kernel<<<(ET + 255) / 256, 256>>>(ei);

    auto conv = [&](const float* ext, int sel, int n) {
        conv_split<<<256, 256>>>(ext, sel, n);
    };
    auto trans = [&](const float* W, int K, int N, int woff) {
        dim3 grid((N + 31) / 32, (K + 31) / 32);
        trans_split<<<grid, 256>>>(W, K, N, woff);
    };
    auto gemm = [&](int woff, const float* bias, float* Cext, int Csel,
                    int M, int N, int K) {
        dim3 grid((N + 127) / 128, (M + 127) / 128);
        mma_gemm<<<grid, 256, SMEM_GEMM>>>(woff, bias, Cext, Csel, M, N, K);
    };
    auto gat = [&](const float* ATT, const float* B, int outsel, int F) {
        size_t shmem = (size_t)(2 * F + CAP) * sizeof(float) + CAP * sizeof(int);
        gat_node<<<NN, 256, shmem>>>(ATT, B, outsel, F);
    };

    // layer 1: 128 -> 1024
    conv(x, BUF_EXT, NN * 128);
    trans(Wl1, 128, 1024, 0);
    trans(Wr1, 128, 1024, 128 * 1024);
    gemm(0,          bl1, nullptr, BUF_XL, NN, 1024, 128);
    gemm(128 * 1024, br1, nullptr, BUF_XR, NN, 1024, 128);
    gat(at1, b1, BUF_H1, 1024);
    // layer 2: 1024 -> 512
    conv(nullptr, BUF_H1, NN * 1024);
    trans(Wl2, 1024, 512, 0);
    trans(Wr2, 1024, 512, 1024 * 512);
    gemm(0,          bl2, nullptr, BUF_XL, NN, 512, 1024);
    gemm(1024 * 512, br2, nullptr, BUF_XR, NN, 512, 1024);
    gat(at2, b2, BUF_H2, 512);
    // layer 3: 512 -> 128
    conv(nullptr, BUF_H2, NN * 512);
    trans(Wl3, 512, 128, 0);
    trans(Wr3, 512, 128, 512 * 128);
    gemm(0,         bl3, nullptr, BUF_XL, NN, 128, 512);
    gemm(512 * 128, br3, nullptr, BUF_XR, NN, 128, 512);
    gat(at3, b3, BUF_H3, 128);
    // classifier: 128 -> 64
    conv(nullptr, BUF_H3, NN * 128);
    trans(Wc, 128, 64, 0);
    gemm(0, bc, out, BUF_EXT, NN, 64, 128);
}

// round 14
// speedup vs baseline: 1.8631x; 1.1952x over previous
#include <cuda_runtime.h>
#include <cuda_bf16.h>
#include <math.h>
#include <stdint.h>

#define NN 10000
#define NE 160000
#define ET (NE + NN)
#define CAP 1024
#define NEG_SLOPE 0.2f

// ---------------- scratch ----------------------------------------------------
__device__ __align__(16) float g_xl[(size_t)NN * 1024];
__device__ __align__(16) float g_xr[(size_t)NN * 1024];
__device__ __align__(16) __nv_bfloat16 g_ah[(size_t)NN * 1024];   // A hi (split act.)
__device__ __align__(16) __nv_bfloat16 g_al[(size_t)NN * 1024];   // A lo
__device__ __align__(16) __nv_bfloat16 g_wh[2 * 1024 * 1024];     // Wt hi [2N,K]
__device__ __align__(16) __nv_bfloat16 g_wl[2 * 1024 * 1024];     // Wt lo
__device__ int   g_cnt[NN];
__device__ int   g_rowptr[NN + 1];
__device__ int   g_cur[NN];
__device__ int   g_srcs[ET];
__device__ float g_efb[ET];
__device__ int   g_is64;

// ---------------- split helpers ----------------------------------------------
__device__ __forceinline__ uint32_t pack_hi2(float a, float b, float& la, float& lb) {
    __nv_bfloat16 ha = __float2bfloat16_rn(a), hb = __float2bfloat16_rn(b);
    la = a - __bfloat162float(ha);
    lb = b - __bfloat162float(hb);
    return ((uint32_t)__bfloat16_as_ushort(hb) << 16) | __bfloat16_as_ushort(ha);
}
__device__ __forceinline__ uint32_t pack2(float a, float b) {
    return ((uint32_t)__bfloat16_as_ushort(__float2bfloat16_rn(b)) << 16)
         | __bfloat16_as_ushort(__float2bfloat16_rn(a));
}

// fp32 -> hi/lo bf16 split (input features only; later layers fused into gat)
__global__ void conv_split(const float* __restrict__ in, int n) {
    for (int i = blockIdx.x * blockDim.x + threadIdx.x; i < n;
         i += gridDim.x * blockDim.x) {
        float v = in[i];
        __nv_bfloat16 h = __float2bfloat16_rn(v);
        g_ah[i] = h;
        g_al[i] = __float2bfloat16_rn(v - __bfloat162float(h));
    }
}

// W [K,N] fp32  ->  Wt hi/lo [N,K] bf16 at row offset woff/K
__global__ void trans_split(const float* __restrict__ W, int K, int N, int woff) {
    __shared__ float t[32][33];
    int n0 = blockIdx.x * 32, k0 = blockIdx.y * 32;
    int tx = threadIdx.x & 31, ty = threadIdx.x >> 5;
    #pragma unroll
    for (int i = 0; i < 32; i += 8) {
        int k = k0 + ty + i, n = n0 + tx;
        t[ty + i][tx] = (k < K && n < N) ? W[(size_t)k * N + n] : 0.f;
    }
    __syncthreads();
    #pragma unroll
    for (int i = 0; i < 32; i += 8) {
        int n = n0 + ty + i, k = k0 + tx;
        if (n < N && k < K) {
            float v = t[tx][ty + i];
            __nv_bfloat16 h = __float2bfloat16_rn(v);
            size_t o = (size_t)woff + (size_t)n * K + k;
            g_wh[o] = h;
            g_wl[o] = __float2bfloat16_rn(v - __bfloat162float(h));
        }
    }
}

// ---------------- mma helpers -------------------------------------------------
__device__ __forceinline__ void mma16816(float* c, const uint32_t* a, const uint32_t* b) {
    asm volatile(
        "mma.sync.aligned.m16n8k16.row.col.f32.bf16.bf16.f32 "
        "{%0,%1,%2,%3}, {%4,%5,%6,%7}, {%8,%9}, {%0,%1,%2,%3};"
        : "+f"(c[0]), "+f"(c[1]), "+f"(c[2]), "+f"(c[3])
        : "r"(a[0]), "r"(a[1]), "r"(a[2]), "r"(a[3]), "r"(b[0]), "r"(b[1]));
}
__device__ __forceinline__ uint32_t smem_u32(const void* p) {
    uint32_t a;
    asm("{ .reg .u64 t; cvta.to.shared.u64 t, %1; cvt.u32.u64 %0, t; }"
        : "=r"(a) : "l"(p));
    return a;
}
__device__ __forceinline__ void cpa8(uint32_t s, const void* g) {
    asm volatile("cp.async.ca.shared.global [%0], [%1], 8;"
                 :: "r"(s), "l"(g) : "memory");
}
#define CP_COMMIT() asm volatile("cp.async.commit_group;" ::: "memory")
#define CP_WAIT(n)  asm volatile("cp.async.wait_group %0;" :: "n"(n) : "memory")

// ---------------- split-bf16 mma.sync GEMM, dual-output ----------------------
// C = A[M,K] @ Wt^T + bias.  Wt combined [N2,K] bf16 hi/lo (N2 = split? 2*halfN : halfN).
// split: cols [0,halfN) -> g_xl, [halfN,2halfN) -> g_xr (tile never straddles).
#define AST 40
#define TILE_B (128 * AST * 2)
#define STAGE_B (4 * TILE_B)
#define SMEM_GEMM (2 * STAGE_B)   // 81920 B

__global__ __launch_bounds__(256) void mma_gemm(
    const float* __restrict__ biasL, const float* __restrict__ biasR,
    float* __restrict__ Cext, int split,
    int M, int halfN, int K)
{
    extern __shared__ char smem[];
    uint32_t sb = smem_u32(smem);

    int N2 = split ? 2 * halfN : halfN;
    int tid = threadIdx.x, lane = tid & 31, wid = tid >> 5;
    int wm = (wid & 1) * 64, wn = (wid >> 1) * 32;
    int brow = blockIdx.y * 128, bcol = blockIdx.x * 128;

    // per-CTA output routing
    bool right = split && (bcol >= halfN);
    float* C = split ? (right ? g_xr : g_xl) : Cext;
    const float* bias = right ? biasR : biasL;
    int cbase = bcol - (right ? halfN : 0);

    float c[4][4][4];
    #pragma unroll
    for (int mi = 0; mi < 4; mi++)
        #pragma unroll
        for (int ni = 0; ni < 4; ni++)
            #pragma unroll
            for (int q = 0; q < 4; q++) c[mi][ni][q] = 0.f;

    int lr = tid >> 1;
    int lk = (tid & 1) * 16;
    bool aok = (brow + lr) < M;
    bool bok = (bcol + lr) < N2;
    const __nv_bfloat16* pAh = g_ah + (size_t)(brow + lr) * K + lk;
    const __nv_bfloat16* pAl = g_al + (size_t)(brow + lr) * K + lk;
    const __nv_bfloat16* pBh = g_wh + (size_t)(bcol + lr) * K + lk;
    const __nv_bfloat16* pBl = g_wl + (size_t)(bcol + lr) * K + lk;
    uint32_t so = (uint32_t)(lr * AST + lk) * 2;

    auto load_stage = [&](int st, int kt) {
        uint32_t s0 = sb + st * STAGE_B + so;
        if (aok) {
            #pragma unroll
            for (int q = 0; q < 4; q++) cpa8(s0 + q * 8, pAh + kt + q * 4);
            #pragma unroll
            for (int q = 0; q < 4; q++) cpa8(s0 + TILE_B + q * 8, pAl + kt + q * 4);
        } else {
            uint2 z = make_uint2(0u, 0u);
            char* d = smem + st * STAGE_B + so;
            #pragma unroll
            for (int q = 0; q < 4; q++) {
                *(uint2*)(d + q * 8) = z;
                *(uint2*)(d + TILE_B + q * 8) = z;
            }
        }
        if (bok) {
            #pragma unroll
            for (int q = 0; q < 4; q++) cpa8(s0 + 2 * TILE_B + q * 8, pBh + kt + q * 4);
            #pragma unroll
            for (int q = 0; q < 4; q++) cpa8(s0 + 3 * TILE_B + q * 8, pBl + kt + q * 4);
        } else {
            uint2 z = make_uint2(0u, 0u);
            char* d = smem + st * STAGE_B + so;
            #pragma unroll
            for (int q = 0; q < 4; q++) {
                *(uint2*)(d + 2 * TILE_B + q * 8) = z;
                *(uint2*)(d + 3 * TILE_B + q * 8) = z;
            }
        }
    };

    int r = lane >> 2, cc = (lane & 3) * 2;
    int nch = K >> 5;

    load_stage(0, 0);
    CP_COMMIT();

    for (int t = 0; t < nch; t++) {
        if (t + 1 < nch) {
            load_stage((t + 1) & 1, (t + 1) * 32);
            CP_COMMIT();
            CP_WAIT(1);
        } else {
            CP_WAIT(0);
        }
        __syncthreads();

        const char* stb = smem + (t & 1) * STAGE_B;
        const uint16_t* sAh = (const uint16_t*)(stb);
        const uint16_t* sAl = (const uint16_t*)(stb + TILE_B);
        const uint16_t* sBh = (const uint16_t*)(stb + 2 * TILE_B);
        const uint16_t* sBl = (const uint16_t*)(stb + 3 * TILE_B);

        #pragma unroll
        for (int ks = 0; ks < 2; ks++) {
            int kb = ks * 16;
            uint32_t ah[4][4], al[4][4], bh[4][2], bl[4][2];
            #pragma unroll
            for (int mi = 0; mi < 4; mi++) {
                const uint16_t* ph = sAh + (wm + mi * 16 + r) * AST + kb + cc;
                const uint16_t* pl = sAl + (wm + mi * 16 + r) * AST + kb + cc;
                ah[mi][0] = *(const uint32_t*)ph;
                ah[mi][1] = *(const uint32_t*)(ph + 8 * AST);
                ah[mi][2] = *(const uint32_t*)(ph + 8);
                ah[mi][3] = *(const uint32_t*)(ph + 8 * AST + 8);
                al[mi][0] = *(const uint32_t*)pl;
                al[mi][1] = *(const uint32_t*)(pl + 8 * AST);
                al[mi][2] = *(const uint32_t*)(pl + 8);
                al[mi][3] = *(const uint32_t*)(pl + 8 * AST + 8);
            }
            #pragma unroll
            for (int ni = 0; ni < 4; ni++) {
                const uint16_t* ph = sBh + (wn + ni * 8 + r) * AST + kb + cc;
                const uint16_t* pl = sBl + (wn + ni * 8 + r) * AST + kb + cc;
                bh[ni][0] = *(const uint32_t*)ph;
                bh[ni][1] = *(const uint32_t*)(ph + 8);
                bl[ni][0] = *(const uint32_t*)pl;
                bl[ni][1] = *(const uint32_t*)(pl + 8);
            }
            #pragma unroll
            for (int mi = 0; mi < 4; mi++)
                #pragma unroll
                for (int ni = 0; ni < 4; ni++) {
                    mma16816(c[mi][ni], ah[mi], bh[ni]);
                    mma16816(c[mi][ni], ah[mi], bl[ni]);
                    mma16816(c[mi][ni], al[mi], bh[ni]);
                }
        }
        __syncthreads();
    }

    // epilogue
    int r0 = brow + wm + r;
    int c0 = cbase + wn + cc;
    #pragma unroll
    for (int mi = 0; mi < 4; mi++) {
        #pragma unroll
        for (int ni = 0; ni < 4; ni++) {
            int col = c0 + ni * 8;
            if (col >= halfN) continue;
            float bx = bias[col], by = bias[col + 1];
            int row0 = r0 + mi * 16;
            if (row0 < M)
                *(float2*)(C + (size_t)row0 * halfN + col) =
                    make_float2(c[mi][ni][0] + bx, c[mi][ni][1] + by);
            int row1 = row0 + 8;
            if (row1 < M)
                *(float2*)(C + (size_t)row1 * halfN + col) =
                    make_float2(c[mi][ni][2] + bx, c[mi][ni][3] + by);
        }
    }
}

// ---------------- zero counters + dtype flag ---------------------------------
__global__ void zero_counters() {
    int i = blockIdx.x * blockDim.x + threadIdx.x;
    if (i < NN) { g_cnt[i] = 0; g_cur[i] = 0; }
    if (i == 0) g_is64 = 1;
}

__global__ void detect_dtype(const long long* __restrict__ ei) {
    bool bad = false;
    for (int i = blockIdx.x * blockDim.x + threadIdx.x; i < NE;
         i += gridDim.x * blockDim.x) {
        long long v = ei[i];
        if (v < 0 || v >= NN) bad = true;
    }
    if (bad) g_is64 = 0;
}

__device__ __forceinline__ int edge_at(const void* ei, int idx) {
    return g_is64 ? (int)((const long long*)ei)[idx]
                  : ((const int*)ei)[idx];
}

// ---------------- CSR build --------------------------------------------------
__global__ void count_kernel(const void* __restrict__ ei) {
    int e = blockIdx.x * blockDim.x + threadIdx.x;
    if (e >= ET) return;
    int dst = (e < NE) ? edge_at(ei, NE + e) : (e - NE);
    if ((unsigned)dst < NN) atomicAdd(&g_cnt[dst], 1);
}

__global__ void scan_kernel() {
    __shared__ int part[1024];
    int t = threadIdx.x;
    const int CH = (NN + 1023) / 1024;
    int base = t * CH;
    int s = 0;
    for (int k = 0; k < CH; k++) {
        int i = base + k;
        if (i < NN) s += g_cnt[i];
    }
    part[t] = s;
    __syncthreads();
    for (int off = 1; off < 1024; off <<= 1) {
        int v = (t >= off) ? part[t - off] : 0;
        __syncthreads();
        part[t] += v;
        __syncthreads();
    }
    int run = (t == 0) ? 0 : part[t - 1];
    for (int k = 0; k < CH; k++) {
        int i = base + k;
        if (i < NN) { run += g_cnt[i]; g_rowptr[i + 1] = run; }
    }
    if (t == 0) g_rowptr[0] = 0;
}

__global__ void fill_kernel(const void* __restrict__ ei) {
    int e = blockIdx.x * blockDim.x + threadIdx.x;
    if (e >= ET) return;
    int src, dst;
    if (e < NE) { src = edge_at(ei, e); dst = edge_at(ei, NE + e); }
    else        { src = dst = e - NE; }
    if ((unsigned)src >= NN || (unsigned)dst >= NN) return;
    int pos = atomicAdd(&g_cur[dst], 1);
    g_srcs[g_rowptr[dst] + pos] = src;
}

// ---------------- fused GATv2 edge stage + bf16 split epilogue ---------------
// Output (post-relu) is written directly as bf16 hi/lo into g_ah/g_al
// (feeds the next layer's GEMM); fp32 h buffer eliminated.
__global__ __launch_bounds__(256) void gat_node(
    const float* __restrict__ att, const float* __restrict__ bias, int F)
{
    const float* xl = g_xl;
    const float* xr = g_xr;

    int v = blockIdx.x;
    int start = g_rowptr[v];
    int deg   = g_rowptr[v + 1] - start;
    int F4 = F >> 2;

    extern __shared__ float sh[];
    float* s_xr  = sh;
    float* s_att = sh + F;
    float* s_e   = sh + 2 * F;
    int*   s_src = (int*)(sh + 2 * F + CAP);
    __shared__ float red[32];
    __shared__ float s_bcast;

    int tid = threadIdx.x, bs = blockDim.x;
    int lane = tid & 31, wid = tid >> 5, nw = bs >> 5;

    {
        const float4* xr4  = (const float4*)(xr + (size_t)v * F);
        const float4* att4 = (const float4*)att;
        for (int f = tid; f < F4; f += bs) {
            ((float4*)s_xr)[f]  = xr4[f];
            ((float4*)s_att)[f] = att4[f];
        }
    }
    for (int j = tid; j < deg && j < CAP; j += bs) s_src[j] = g_srcs[start + j];
    __syncthreads();

    for (int j = wid; j < deg; j += nw) {
        int s = (j < CAP) ? s_src[j] : g_srcs[start + j];
        const float4* xl4 = (const float4*)(xl + (size_t)s * F);
        float acc = 0.f;
        for (int f = lane; f < F4; f += 32) {
            float4 a = xl4[f];
            float4 r = ((const float4*)s_xr)[f];
            float4 w = ((const float4*)s_att)[f];
            float m;
            m = a.x + r.x; m = (m > 0.f) ? m : m * NEG_SLOPE; acc += m * w.x;
            m = a.y + r.y; m = (m > 0.f) ? m : m * NEG_SLOPE; acc += m * w.y;
            m = a.z + r.z; m = (m > 0.f) ? m : m * NEG_SLOPE; acc += m * w.z;
            m = a.w + r.w; m = (m > 0.f) ? m : m * NEG_SLOPE; acc += m * w.w;
        }
        #pragma unroll
        for (int o = 16; o; o >>= 1) acc += __shfl_down_sync(0xffffffffu, acc, o);
        if (lane == 0) {
            if (j < CAP) s_e[j] = acc;
            else         g_efb[start + j] = acc;
        }
    }
    __syncthreads();

    float mx = -INFINITY;
    for (int j = tid; j < deg; j += bs)
        mx = fmaxf(mx, (j < CAP) ? s_e[j] : g_efb[start + j]);
    #pragma unroll
    for (int o = 16; o; o >>= 1) mx = fmaxf(mx, __shfl_down_sync(0xffffffffu, mx, o));
    if (lane == 0) red[wid] = mx;
    __syncthreads();
    if (wid == 0) {
        float m2 = (lane < nw) ? red[lane] : -INFINITY;
        #pragma unroll
        for (int o = 16; o; o >>= 1) m2 = fmaxf(m2, __shfl_down_sync(0xffffffffu, m2, o));
        if (lane == 0) s_bcast = m2;
    }
    __syncthreads();
    float M = s_bcast;

    float zs = 0.f;
    for (int j = tid; j < deg; j += bs) {
        float e  = (j < CAP) ? s_e[j] : g_efb[start + j];
        float ez = __expf(e - M);
        if (j < CAP) s_e[j] = ez; else g_efb[start + j] = ez;
        zs += ez;
    }
    #pragma unroll
    for (int o = 16; o; o >>= 1) zs += __shfl_down_sync(0xffffffffu, zs, o);
    if (lane == 0) red[wid] = zs;
    __syncthreads();
    if (wid == 0) {
        float z2 = (lane < nw) ? red[lane] : 0.f;
        #pragma unroll
        for (int o = 16; o; o >>= 1) z2 += __shfl_down_sync(0xffffffffu, z2, o);
        if (lane == 0) s_bcast = z2;
    }
    __syncthreads();
    float inv = 1.f / s_bcast;

    const float4* bias4 = (const float4*)bias;
    for (int f = tid; f < F4; f += bs) {
        float4 acc = make_float4(0.f, 0.f, 0.f, 0.f);
        for (int j = 0; j < deg; j++) {
            int s    = (j < CAP) ? s_src[j] : g_srcs[start + j];
            float ez = (j < CAP) ? s_e[j]   : g_efb[start + j];
            float4 xv = ((const float4*)(xl + (size_t)s * F))[f];
            acc.x += ez * xv.x;
            acc.y += ez * xv.y;
            acc.z += ez * xv.z;
            acc.w += ez * xv.w;
        }
        float4 bv = bias4[f];
        float4 o;
        o.x = fmaxf(acc.x * inv + bv.x, 0.f);
        o.y = fmaxf(acc.y * inv + bv.y, 0.f);
        o.z = fmaxf(acc.z * inv + bv.z, 0.f);
        o.w = fmaxf(acc.w * inv + bv.w, 0.f);
        // write bf16 hi/lo split directly (next GEMM input)
        size_t idx = (size_t)v * F + f * 4;
        float lx, ly, lz, lw;
        uint32_t h0 = pack_hi2(o.x, o.y, lx, ly);
        uint32_t h1 = pack_hi2(o.z, o.w, lz, lw);
        *(uint2*)(g_ah + idx) = make_uint2(h0, h1);
        *(uint2*)(g_al + idx) = make_uint2(pack2(lx, ly), pack2(lz, lw));
    }
}

// ---------------- host --------------------------------------------------------
extern "C" void kernel_launch(void* const* d_in, const int* in_sizes, int n_in,
                              void* d_out, int out_size) {
    (void)in_sizes; (void)n_in; (void)out_size;

    const float* x  = (const float*)d_in[0];
    const void*  ei = d_in[1];
    const float *Wl1 = (const float*)d_in[2],  *bl1 = (const float*)d_in[3];
    const float *Wr1 = (const float*)d_in[4],  *br1 = (const float*)d_in[5];
    const float *at1 = (const float*)d_in[6],  *b1  = (const float*)d_in[7];
    const float *Wl2 = (const float*)d_in[8],  *bl2 = (const float*)d_in[9];
    const float *Wr2 = (const float*)d_in[10], *br2 = (const float*)d_in[11];
    const float *at2 = (const float*)d_in[12], *b2  = (const float*)d_in[13];
    const float *Wl3 = (const float*)d_in[14], *bl3 = (const float*)d_in[15];
    const float *Wr3 = (const float*)d_in[16], *br3 = (const float*)d_in[17];
    const float *at3 = (const float*)d_in[18], *b3  = (const float*)d_in[19];
    const float *Wc  = (const float*)d_in[20], *bc  = (const float*)d_in[21];
    float* out = (float*)d_out;

    cudaFuncSetAttribute(mma_gemm,
                         cudaFuncAttributeMaxDynamicSharedMemorySize, SMEM_GEMM);

    zero_counters<<<(NN + 255) / 256, 256>>>();
    detect_dtype<<<64, 256>>>((const long long*)ei);
    count_kernel<<<(ET + 255) / 256, 256>>>(ei);
    scan_kernel<<<1, 1024>>>();
    fill_kernel<<<(ET + 255) / 256, 256>>>(ei);

    auto trans = [&](const float* W, int K, int N, int woff) {
        dim3 grid((N + 31) / 32, (K + 31) / 32);
        trans_split<<<grid, 256>>>(W, K, N, woff);
    };
    // dual GEMM: C_l = A @ Wl + bl -> g_xl ; C_r = A @ Wr + br -> g_xr
    auto gemm2 = [&](const float* bl, const float* br, int halfN, int K) {
        dim3 grid((2 * halfN + 127) / 128, (NN + 127) / 128);
        mma_gemm<<<grid, 256, SMEM_GEMM>>>(bl, br, nullptr, 1, NN, halfN, K);
    };
    auto gemm1 = [&](const float* b, float* C, int N, int K) {
        dim3 grid((N + 127) / 128, (NN + 127) / 128);
        mma_gemm<<<grid, 256, SMEM_GEMM>>>(b, b, C, 0, NN, N, K);
    };
    auto gat = [&](const float* ATT, const float* B, int F) {
        size_t shmem = (size_t)(2 * F + CAP) * sizeof(float) + CAP * sizeof(int);
        gat_node<<<NN, 256, shmem>>>(ATT, B, F);
    };

    // layer 1: 128 -> 1024
    conv_split<<<256, 256>>>(x, NN * 128);
    trans(Wl1, 128, 1024, 0);
    trans(Wr1, 128, 1024, 1024 * 128);
    gemm2(bl1, br1, 1024, 128);
    gat(at1, b1, 1024);
    // layer 2: 1024 -> 512
    trans(Wl2, 1024, 512, 0);
    trans(Wr2, 1024, 512, 512 * 1024);
    gemm2(bl2, br2, 512, 1024);
    gat(at2, b2, 512);
    // layer 3: 512 -> 128
    trans(Wl3, 512, 128, 0);
    trans(Wr3, 512, 128, 128 * 512);
    gemm2(bl3, br3, 128, 512);
    gat(at3, b3, 128);
    // classifier: 128 -> 64
    trans(Wc, 128, 64, 0);
    gemm1(bc, out, 64, 128);
}

// round 15
// speedup vs baseline: 2.0536x; 1.1023x over previous
#include <cuda_runtime.h>
#include <cuda_bf16.h>
#include <math.h>
#include <stdint.h>

#define NN 10000
#define NE 160000
#define ET (NE + NN)
#define CAP 1024
#define NEG_SLOPE 0.2f

// ---------------- scratch ----------------------------------------------------
__device__ __align__(16) float g_xl[(size_t)NN * 1024];
__device__ __align__(16) float g_xr[(size_t)NN * 1024];
__device__ __align__(16) __nv_bfloat16 g_ah[(size_t)NN * 1024];   // A hi (split act.)
__device__ __align__(16) __nv_bfloat16 g_al[(size_t)NN * 1024];   // A lo
__device__ __align__(16) __nv_bfloat16 g_wh[2 * 1024 * 1024];     // Wt hi [2N,K]
__device__ __align__(16) __nv_bfloat16 g_wl[2 * 1024 * 1024];     // Wt lo
__device__ int   g_cnt[NN];
__device__ int   g_rowptr[NN + 1];
__device__ int   g_cur[NN];
__device__ int   g_srcs[ET];
__device__ float g_efb[ET];
__device__ int   g_is64;

// ---------------- split helpers ----------------------------------------------
__device__ __forceinline__ uint32_t pack_hi2(float a, float b, float& la, float& lb) {
    __nv_bfloat16 ha = __float2bfloat16_rn(a), hb = __float2bfloat16_rn(b);
    la = a - __bfloat162float(ha);
    lb = b - __bfloat162float(hb);
    return ((uint32_t)__bfloat16_as_ushort(hb) << 16) | __bfloat16_as_ushort(ha);
}
__device__ __forceinline__ uint32_t pack2(float a, float b) {
    return ((uint32_t)__bfloat16_as_ushort(__float2bfloat16_rn(b)) << 16)
         | __bfloat16_as_ushort(__float2bfloat16_rn(a));
}

__global__ void conv_split(const float* __restrict__ in, int n) {
    for (int i = blockIdx.x * blockDim.x + threadIdx.x; i < n;
         i += gridDim.x * blockDim.x) {
        float v = in[i];
        __nv_bfloat16 h = __float2bfloat16_rn(v);
        g_ah[i] = h;
        g_al[i] = __float2bfloat16_rn(v - __bfloat162float(h));
    }
}

// W [K,N] fp32  ->  Wt hi/lo [N,K] bf16 at row offset woff/K
__global__ void trans_split(const float* __restrict__ W, int K, int N, int woff) {
    __shared__ float t[32][33];
    int n0 = blockIdx.x * 32, k0 = blockIdx.y * 32;
    int tx = threadIdx.x & 31, ty = threadIdx.x >> 5;
    #pragma unroll
    for (int i = 0; i < 32; i += 8) {
        int k = k0 + ty + i, n = n0 + tx;
        t[ty + i][tx] = (k < K && n < N) ? W[(size_t)k * N + n] : 0.f;
    }
    __syncthreads();
    #pragma unroll
    for (int i = 0; i < 32; i += 8) {
        int n = n0 + ty + i, k = k0 + tx;
        if (n < N && k < K) {
            float v = t[tx][ty + i];
            __nv_bfloat16 h = __float2bfloat16_rn(v);
            size_t o = (size_t)woff + (size_t)n * K + k;
            g_wh[o] = h;
            g_wl[o] = __float2bfloat16_rn(v - __bfloat162float(h));
        }
    }
}

// ---------------- mma helpers -------------------------------------------------
__device__ __forceinline__ void mma16816(float* c, const uint32_t* a, const uint32_t* b) {
    asm volatile(
        "mma.sync.aligned.m16n8k16.row.col.f32.bf16.bf16.f32 "
        "{%0,%1,%2,%3}, {%4,%5,%6,%7}, {%8,%9}, {%0,%1,%2,%3};"
        : "+f"(c[0]), "+f"(c[1]), "+f"(c[2]), "+f"(c[3])
        : "r"(a[0]), "r"(a[1]), "r"(a[2]), "r"(a[3]), "r"(b[0]), "r"(b[1]));
}
__device__ __forceinline__ void ldsm_x4(uint32_t* r, uint32_t addr) {
    asm volatile("ldmatrix.sync.aligned.m8n8.x4.shared.b16 {%0,%1,%2,%3}, [%4];"
        : "=r"(r[0]), "=r"(r[1]), "=r"(r[2]), "=r"(r[3]) : "r"(addr));
}
__device__ __forceinline__ uint32_t smem_u32(const void* p) {
    uint32_t a;
    asm("{ .reg .u64 t; cvta.to.shared.u64 t, %1; cvt.u32.u64 %0, t; }"
        : "=r"(a) : "l"(p));
    return a;
}
__device__ __forceinline__ void cpa8(uint32_t s, const void* g) {
    asm volatile("cp.async.ca.shared.global [%0], [%1], 8;"
                 :: "r"(s), "l"(g) : "memory");
}
#define CP_COMMIT() asm volatile("cp.async.commit_group;" ::: "memory")
#define CP_WAIT(n)  asm volatile("cp.async.wait_group %0;" :: "n"(n) : "memory")

// ---------------- split-bf16 mma.sync GEMM, ldmatrix fragments ---------------
#define AST 40
#define TILE_B (128 * AST * 2)
#define STAGE_B (4 * TILE_B)
#define SMEM_GEMM (2 * STAGE_B)   // 81920 B

__global__ __launch_bounds__(256) void mma_gemm(
    const float* __restrict__ biasL, const float* __restrict__ biasR,
    float* __restrict__ Cext, int split,
    int M, int halfN, int K)
{
    extern __shared__ char smem[];
    uint32_t sb = smem_u32(smem);

    int N2 = split ? 2 * halfN : halfN;
    int tid = threadIdx.x, lane = tid & 31, wid = tid >> 5;
    int wm = (wid & 1) * 64, wn = (wid >> 1) * 32;
    int brow = blockIdx.y * 128, bcol = blockIdx.x * 128;

    bool right = split && (bcol >= halfN);
    float* C = split ? (right ? g_xr : g_xl) : Cext;
    const float* bias = right ? biasR : biasL;
    int cbase = bcol - (right ? halfN : 0);

    float c[4][4][4];
    #pragma unroll
    for (int mi = 0; mi < 4; mi++)
        #pragma unroll
        for (int ni = 0; ni < 4; ni++)
            #pragma unroll
            for (int q = 0; q < 4; q++) c[mi][ni][q] = 0.f;

    int lr = tid >> 1;
    int lk = (tid & 1) * 16;
    bool aok = (brow + lr) < M;
    bool bok = (bcol + lr) < N2;
    const __nv_bfloat16* pAh = g_ah + (size_t)(brow + lr) * K + lk;
    const __nv_bfloat16* pAl = g_al + (size_t)(brow + lr) * K + lk;
    const __nv_bfloat16* pBh = g_wh + (size_t)(bcol + lr) * K + lk;
    const __nv_bfloat16* pBl = g_wl + (size_t)(bcol + lr) * K + lk;
    uint32_t so = (uint32_t)(lr * AST + lk) * 2;

    auto load_stage = [&](int st, int kt) {
        uint32_t s0 = sb + st * STAGE_B + so;
        if (aok) {
            #pragma unroll
            for (int q = 0; q < 4; q++) cpa8(s0 + q * 8, pAh + kt + q * 4);
            #pragma unroll
            for (int q = 0; q < 4; q++) cpa8(s0 + TILE_B + q * 8, pAl + kt + q * 4);
        } else {
            uint2 z = make_uint2(0u, 0u);
            char* d = smem + st * STAGE_B + so;
            #pragma unroll
            for (int q = 0; q < 4; q++) {
                *(uint2*)(d + q * 8) = z;
                *(uint2*)(d + TILE_B + q * 8) = z;
            }
        }
        if (bok) {
            #pragma unroll
            for (int q = 0; q < 4; q++) cpa8(s0 + 2 * TILE_B + q * 8, pBh + kt + q * 4);
            #pragma unroll
            for (int q = 0; q < 4; q++) cpa8(s0 + 3 * TILE_B + q * 8, pBl + kt + q * 4);
        } else {
            uint2 z = make_uint2(0u, 0u);
            char* d = smem + st * STAGE_B + so;
            #pragma unroll
            for (int q = 0; q < 4; q++) {
                *(uint2*)(d + 2 * TILE_B + q * 8) = z;
                *(uint2*)(d + 3 * TILE_B + q * 8) = z;
            }
        }
    };

    // ldmatrix per-lane byte offsets within a stage
    // A (m16k16 -> x4: [r,k0-7],[r+8,k0-7],[r,k8-15],[r+8,k8-15])
    int row_a = (lane & 7) + ((lane >> 3) & 1) * 8;
    int col_a = (lane >> 4) * 8;
    uint32_t aoff[4];
    #pragma unroll
    for (int mi = 0; mi < 4; mi++)
        aoff[mi] = (uint32_t)(((wm + mi * 16 + row_a) * AST + col_a) * 2);
    // B (two n8k16 frags -> x4: [n(ni),k0-7],[n(ni),k8-15],[n(ni+1),k0-7],[n(ni+1),k8-15])
    int row_b = ((lane >> 4) * 8) + (lane & 7);
    int col_b = ((lane >> 3) & 1) * 8;
    uint32_t boff[2];
    #pragma unroll
    for (int nh = 0; nh < 2; nh++)
        boff[nh] = (uint32_t)(((wn + nh * 16 + row_b) * AST + col_b) * 2);

    int r = lane >> 2, cc = (lane & 3) * 2;   // for epilogue
    int nch = K >> 5;

    load_stage(0, 0);
    CP_COMMIT();

    for (int t = 0; t < nch; t++) {
        if (t + 1 < nch) {
            load_stage((t + 1) & 1, (t + 1) * 32);
            CP_COMMIT();
            CP_WAIT(1);
        } else {
            CP_WAIT(0);
        }
        __syncthreads();

        uint32_t sst = sb + (t & 1) * STAGE_B;

        #pragma unroll
        for (int ks = 0; ks < 2; ks++) {
            uint32_t kbb = (uint32_t)(ks * 32);   // 16 k-elems * 2 bytes
            uint32_t ah[4][4], al[4][4], bhv[2][4], blv[2][4];
            #pragma unroll
            for (int mi = 0; mi < 4; mi++) {
                ldsm_x4(ah[mi], sst + aoff[mi] + kbb);
                ldsm_x4(al[mi], sst + TILE_B + aoff[mi] + kbb);
            }
            #pragma unroll
            for (int nh = 0; nh < 2; nh++) {
                ldsm_x4(bhv[nh], sst + 2 * TILE_B + boff[nh] + kbb);
                ldsm_x4(blv[nh], sst + 3 * TILE_B + boff[nh] + kbb);
            }
            #pragma unroll
            for (int mi = 0; mi < 4; mi++)
                #pragma unroll
                for (int ni = 0; ni < 4; ni++) {
                    const uint32_t* bh = &bhv[ni >> 1][(ni & 1) * 2];
                    const uint32_t* bl = &blv[ni >> 1][(ni & 1) * 2];
                    mma16816(c[mi][ni], ah[mi], bh);
                    mma16816(c[mi][ni], ah[mi], bl);
                    mma16816(c[mi][ni], al[mi], bh);
                }
        }
        __syncthreads();
    }

    // epilogue
    int r0 = brow + wm + r;
    int c0 = cbase + wn + cc;
    #pragma unroll
    for (int mi = 0; mi < 4; mi++) {
        #pragma unroll
        for (int ni = 0; ni < 4; ni++) {
            int col = c0 + ni * 8;
            if (col >= halfN) continue;
            float bx = bias[col], by = bias[col + 1];
            int row0 = r0 + mi * 16;
            if (row0 < M)
                *(float2*)(C + (size_t)row0 * halfN + col) =
                    make_float2(c[mi][ni][0] + bx, c[mi][ni][1] + by);
            int row1 = row0 + 8;
            if (row1 < M)
                *(float2*)(C + (size_t)row1 * halfN + col) =
                    make_float2(c[mi][ni][2] + bx, c[mi][ni][3] + by);
        }
    }
}

// ---------------- zero counters + dtype flag ---------------------------------
__global__ void zero_counters() {
    int i = blockIdx.x * blockDim.x + threadIdx.x;
    if (i < NN) { g_cnt[i] = 0; g_cur[i] = 0; }
    if (i == 0) g_is64 = 1;
}

__global__ void detect_dtype(const long long* __restrict__ ei) {
    bool bad = false;
    for (int i = blockIdx.x * blockDim.x + threadIdx.x; i < NE;
         i += gridDim.x * blockDim.x) {
        long long v = ei[i];
        if (v < 0 || v >= NN) bad = true;
    }
    if (bad) g_is64 = 0;
}

__device__ __forceinline__ int edge_at(const void* ei, int idx) {
    return g_is64 ? (int)((const long long*)ei)[idx]
                  : ((const int*)ei)[idx];
}

// ---------------- CSR build --------------------------------------------------
__global__ void count_kernel(const void* __restrict__ ei) {
    int e = blockIdx.x * blockDim.x + threadIdx.x;
    if (e >= ET) return;
    int dst = (e < NE) ? edge_at(ei, NE + e) : (e - NE);
    if ((unsigned)dst < NN) atomicAdd(&g_cnt[dst], 1);
}

__global__ void scan_kernel() {
    __shared__ int part[1024];
    int t = threadIdx.x;
    const int CH = (NN + 1023) / 1024;
    int base = t * CH;
    int s = 0;
    for (int k = 0; k < CH; k++) {
        int i = base + k;
        if (i < NN) s += g_cnt[i];
    }
    part[t] = s;
    __syncthreads();
    for (int off = 1; off < 1024; off <<= 1) {
        int v = (t >= off) ? part[t - off] : 0;
        __syncthreads();
        part[t] += v;
        __syncthreads();
    }
    int run = (t == 0) ? 0 : part[t - 1];
    for (int k = 0; k < CH; k++) {
        int i = base + k;
        if (i < NN) { run += g_cnt[i]; g_rowptr[i + 1] = run; }
    }
    if (t == 0) g_rowptr[0] = 0;
}

__global__ void fill_kernel(const void* __restrict__ ei) {
    int e = blockIdx.x * blockDim.x + threadIdx.x;
    if (e >= ET) return;
    int src, dst;
    if (e < NE) { src = edge_at(ei, e); dst = edge_at(ei, NE + e); }
    else        { src = dst = e - NE; }
    if ((unsigned)src >= NN || (unsigned)dst >= NN) return;
    int pos = atomicAdd(&g_cur[dst], 1);
    g_srcs[g_rowptr[dst] + pos] = src;
}

// ---------------- fused GATv2 edge stage + bf16 split epilogue ---------------
__global__ __launch_bounds__(256) void gat_node(
    const float* __restrict__ att, const float* __restrict__ bias, int F)
{
    const float* xl = g_xl;
    const float* xr = g_xr;

    int v = blockIdx.x;
    int start = g_rowptr[v];
    int deg   = g_rowptr[v + 1] - start;
    int F4 = F >> 2;

    extern __shared__ float sh[];
    float* s_xr  = sh;
    float* s_att = sh + F;
    float* s_e   = sh + 2 * F;
    int*   s_src = (int*)(sh + 2 * F + CAP);
    __shared__ float red[32];
    __shared__ float s_bcast;

    int tid = threadIdx.x, bs = blockDim.x;
    int lane = tid & 31, wid = tid >> 5, nw = bs >> 5;

    {
        const float4* xr4  = (const float4*)(xr + (size_t)v * F);
        const float4* att4 = (const float4*)att;
        for (int f = tid; f < F4; f += bs) {
            ((float4*)s_xr)[f]  = xr4[f];
            ((float4*)s_att)[f] = att4[f];
        }
    }
    for (int j = tid; j < deg && j < CAP; j += bs) s_src[j] = g_srcs[start + j];
    __syncthreads();

    for (int j = wid; j < deg; j += nw) {
        int s = (j < CAP) ? s_src[j] : g_srcs[start + j];
        const float4* xl4 = (const float4*)(xl + (size_t)s * F);
        float acc = 0.f;
        for (int f = lane; f < F4; f += 32) {
            float4 a = xl4[f];
            float4 r = ((const float4*)s_xr)[f];
            float4 w = ((const float4*)s_att)[f];
            float m;
            m = a.x + r.x; m = (m > 0.f) ? m : m * NEG_SLOPE; acc += m * w.x;
            m = a.y + r.y; m = (m > 0.f) ? m : m * NEG_SLOPE; acc += m * w.y;
            m = a.z + r.z; m = (m > 0.f) ? m : m * NEG_SLOPE; acc += m * w.z;
            m = a.w + r.w; m = (m > 0.f) ? m : m * NEG_SLOPE; acc += m * w.w;
        }
        #pragma unroll
        for (int o = 16; o; o >>= 1) acc += __shfl_down_sync(0xffffffffu, acc, o);
        if (lane == 0) {
            if (j < CAP) s_e[j] = acc;
            else         g_efb[start + j] = acc;
        }
    }
    __syncthreads();

    float mx = -INFINITY;
    for (int j = tid; j < deg; j += bs)
        mx = fmaxf(mx, (j < CAP) ? s_e[j] : g_efb[start + j]);
    #pragma unroll
    for (int o = 16; o; o >>= 1) mx = fmaxf(mx, __shfl_down_sync(0xffffffffu, mx, o));
    if (lane == 0) red[wid] = mx;
    __syncthreads();
    if (wid == 0) {
        float m2 = (lane < nw) ? red[lane] : -INFINITY;
        #pragma unroll
        for (int o = 16; o; o >>= 1) m2 = fmaxf(m2, __shfl_down_sync(0xffffffffu, m2, o));
        if (lane == 0) s_bcast = m2;
    }
    __syncthreads();
    float M = s_bcast;

    float zs = 0.f;
    for (int j = tid; j < deg; j += bs) {
        float e  = (j < CAP) ? s_e[j] : g_efb[start + j];
        float ez = __expf(e - M);
        if (j < CAP) s_e[j] = ez; else g_efb[start + j] = ez;
        zs += ez;
    }
    #pragma unroll
    for (int o = 16; o; o >>= 1) zs += __shfl_down_sync(0xffffffffu, zs, o);
    if (lane == 0) red[wid] = zs;
    __syncthreads();
    if (wid == 0) {
        float z2 = (lane < nw) ? red[lane] : 0.f;
        #pragma unroll
        for (int o = 16; o; o >>= 1) z2 += __shfl_down_sync(0xffffffffu, z2, o);
        if (lane == 0) s_bcast = z2;
    }
    __syncthreads();
    float inv = 1.f / s_bcast;

    const float4* bias4 = (const float4*)bias;
    for (int f = tid; f < F4; f += bs) {
        float4 acc = make_float4(0.f, 0.f, 0.f, 0.f);
        for (int j = 0; j < deg; j++) {
            int s    = (j < CAP) ? s_src[j] : g_srcs[start + j];
            float ez = (j < CAP) ? s_e[j]   : g_efb[start + j];
            float4 xv = ((const float4*)(xl + (size_t)s * F))[f];
            acc.x += ez * xv.x;
            acc.y += ez * xv.y;
            acc.z += ez * xv.z;
            acc.w += ez * xv.w;
        }
        float4 bv = bias4[f];
        float4 o;
        o.x = fmaxf(acc.x * inv + bv.x, 0.f);
        o.y = fmaxf(acc.y * inv + bv.y, 0.f);
        o.z = fmaxf(acc.z * inv + bv.z, 0.f);
        o.w = fmaxf(acc.w * inv + bv.w, 0.f);
        size_t idx = (size_t)v * F + f * 4;
        float lx, ly, lz, lw;
        uint32_t h0 = pack_hi2(o.x, o.y, lx, ly);
        uint32_t h1 = pack_hi2(o.z, o.w, lz, lw);
        *(uint2*)(g_ah + idx) = make_uint2(h0, h1);
        *(uint2*)(g_al + idx) = make_uint2(pack2(lx, ly), pack2(lz, lw));
    }
}

// ---------------- host --------------------------------------------------------
extern "C" void kernel_launch(void* const* d_in, const int* in_sizes, int n_in,
                              void* d_out, int out_size) {
    (void)in_sizes; (void)n_in; (void)out_size;

    const float* x  = (const float*)d_in[0];
    const void*  ei = d_in[1];
    const float *Wl1 = (const float*)d_in[2],  *bl1 = (const float*)d_in[3];
    const float *Wr1 = (const float*)d_in[4],  *br1 = (const float*)d_in[5];
    const float *at1 = (const float*)d_in[6],  *b1  = (const float*)d_in[7];
    const float *Wl2 = (const float*)d_in[8],  *bl2 = (const float*)d_in[9];
    const float *Wr2 = (const float*)d_in[10], *br2 = (const float*)d_in[11];
    const float *at2 = (const float*)d_in[12], *b2  = (const float*)d_in[13];
    const float *Wl3 = (const float*)d_in[14], *bl3 = (const float*)d_in[15];
    const float *Wr3 = (const float*)d_in[16], *br3 = (const float*)d_in[17];
    const float *at3 = (const float*)d_in[18], *b3  = (const float*)d_in[19];
    const float *Wc  = (const float*)d_in[20], *bc  = (const float*)d_in[21];
    float* out = (float*)d_out;

    cudaFuncSetAttribute(mma_gemm,
                         cudaFuncAttributeMaxDynamicSharedMemorySize, SMEM_GEMM);

    zero_counters<<<(NN + 255) / 256, 256>>>();
    detect_dtype<<<64, 256>>>((const long long*)ei);
    count_kernel<<<(ET + 255) / 256, 256>>>(ei);
    scan_kernel<<<1, 1024>>>();
    fill_kernel<<<(ET + 255) / 256, 256>>>(ei);

    auto trans = [&](const float* W, int K, int N, int woff) {
        dim3 grid((N + 31) / 32, (K + 31) / 32);
        trans_split<<<grid, 256>>>(W, K, N, woff);
    };
    auto gemm2 = [&](const float* bl, const float* br, int halfN, int K) {
        dim3 grid((2 * halfN + 127) / 128, (NN + 127) / 128);
        mma_gemm<<<grid, 256, SMEM_GEMM>>>(bl, br, nullptr, 1, NN, halfN, K);
    };
    auto gemm1 = [&](const float* b, float* C, int N, int K) {
        dim3 grid((N + 127) / 128, (NN + 127) / 128);
        mma_gemm<<<grid, 256, SMEM_GEMM>>>(b, b, C, 0, NN, N, K);
    };
    auto gat = [&](const float* ATT, const float* B, int F) {
        size_t shmem = (size_t)(2 * F + CAP) * sizeof(float) + CAP * sizeof(int);
        gat_node<<<NN, 256, shmem>>>(ATT, B, F);
    };

    // layer 1: 128 -> 1024
    conv_split<<<256, 256>>>(x, NN * 128);
    trans(Wl1, 128, 1024, 0);
    trans(Wr1, 128, 1024, 1024 * 128);
    gemm2(bl1, br1, 1024, 128);
    gat(at1, b1, 1024);
    // layer 2: 1024 -> 512
    trans(Wl2, 1024, 512, 0);
    trans(Wr2, 1024, 512, 512 * 1024);
    gemm2(bl2, br2, 512, 1024);
    gat(at2, b2, 512);
    // layer 3: 512 -> 128
    trans(Wl3, 512, 128, 0);
    trans(Wr3, 512, 128, 128 * 512);
    gemm2(bl3, br3, 128, 512);
    gat(at3, b3, 128);
    // classifier: 128 -> 64
    trans(Wc, 128, 64, 0);
    gemm1(bc, out, 64, 128);
}

// round 16
// speedup vs baseline: 2.1589x; 1.0512x over previous
#include <cuda_runtime.h>
#include <cuda_bf16.h>
#include <math.h>
#include <stdint.h>

#define NN 10000
#define NE 160000
#define ET (NE + NN)
#define CAP 1024
#define NEG_SLOPE 0.2f

// weight offsets in g_wh/g_wl (elements); Wl/Wr contiguous per layer
#define O1 0
#define O2 (O1 + 2 * 128 * 1024)
#define O3 (O2 + 2 * 1024 * 512)
#define OC (O3 + 2 * 512 * 128)

// ---------------- scratch ----------------------------------------------------
__device__ __align__(16) float g_xl[(size_t)NN * 1024];
__device__ __align__(16) float g_xr[(size_t)NN * 1024];
__device__ __align__(16) __nv_bfloat16 g_ah[(size_t)NN * 1024];
__device__ __align__(16) __nv_bfloat16 g_al[(size_t)NN * 1024];
__device__ __align__(16) __nv_bfloat16 g_wh[2 * 1024 * 1024];
__device__ __align__(16) __nv_bfloat16 g_wl[2 * 1024 * 1024];
__device__ int   g_cnt[NN];
__device__ int   g_rowptr[NN + 1];
__device__ int   g_cur[NN];
__device__ int   g_srcs[ET];
__device__ float g_efb[ET];
__device__ int   g_is64 = 1;

// ---------------- split helpers ----------------------------------------------
__device__ __forceinline__ uint32_t pack_hi2(float a, float b, float& la, float& lb) {
    __nv_bfloat16 ha = __float2bfloat16_rn(a), hb = __float2bfloat16_rn(b);
    la = a - __bfloat162float(ha);
    lb = b - __bfloat162float(hb);
    return ((uint32_t)__bfloat16_as_ushort(hb) << 16) | __bfloat16_as_ushort(ha);
}
__device__ __forceinline__ uint32_t pack2(float a, float b) {
    return ((uint32_t)__bfloat16_as_ushort(__float2bfloat16_rn(b)) << 16)
         | __bfloat16_as_ushort(__float2bfloat16_rn(a));
}

__global__ void conv_split(const float* __restrict__ in, int n) {
    for (int i = blockIdx.x * blockDim.x + threadIdx.x; i < n;
         i += gridDim.x * blockDim.x) {
        float v = in[i];
        __nv_bfloat16 h = __float2bfloat16_rn(v);
        g_ah[i] = h;
        g_al[i] = __float2bfloat16_rn(v - __bfloat162float(h));
    }
}

// All weights transposed+split in ONE launch. grid.z selects the weight.
__global__ void trans_all(
    const float* __restrict__ W1l, const float* __restrict__ W1r,
    const float* __restrict__ W2l, const float* __restrict__ W2r,
    const float* __restrict__ W3l, const float* __restrict__ W3r,
    const float* __restrict__ Wc)
{
    const float* W;
    int K, N, woff;
    switch (blockIdx.z) {
        case 0: W = W1l; K = 128;  N = 1024; woff = O1;                break;
        case 1: W = W1r; K = 128;  N = 1024; woff = O1 + 128 * 1024;   break;
        case 2: W = W2l; K = 1024; N = 512;  woff = O2;                break;
        case 3: W = W2r; K = 1024; N = 512;  woff = O2 + 1024 * 512;   break;
        case 4: W = W3l; K = 512;  N = 128;  woff = O3;                break;
        case 5: W = W3r; K = 512;  N = 128;  woff = O3 + 512 * 128;    break;
        default: W = Wc; K = 128;  N = 64;   woff = OC;                break;
    }
    int n0 = blockIdx.x * 32, k0 = blockIdx.y * 32;
    if (n0 >= N || k0 >= K) return;

    __shared__ float t[32][33];
    int tx = threadIdx.x & 31, ty = threadIdx.x >> 5;
    #pragma unroll
    for (int i = 0; i < 32; i += 8) {
        int k = k0 + ty + i, n = n0 + tx;
        t[ty + i][tx] = (k < K && n < N) ? W[(size_t)k * N + n] : 0.f;
    }
    __syncthreads();
    #pragma unroll
    for (int i = 0; i < 32; i += 8) {
        int n = n0 + ty + i, k = k0 + tx;
        if (n < N && k < K) {
            float v = t[tx][ty + i];
            __nv_bfloat16 h = __float2bfloat16_rn(v);
            size_t o = (size_t)woff + (size_t)n * K + k;
            g_wh[o] = h;
            g_wl[o] = __float2bfloat16_rn(v - __bfloat162float(h));
        }
    }
}

// ---------------- mma helpers -------------------------------------------------
__device__ __forceinline__ void mma16816(float* c, const uint32_t* a, const uint32_t* b) {
    asm volatile(
        "mma.sync.aligned.m16n8k16.row.col.f32.bf16.bf16.f32 "
        "{%0,%1,%2,%3}, {%4,%5,%6,%7}, {%8,%9}, {%0,%1,%2,%3};"
        : "+f"(c[0]), "+f"(c[1]), "+f"(c[2]), "+f"(c[3])
        : "r"(a[0]), "r"(a[1]), "r"(a[2]), "r"(a[3]), "r"(b[0]), "r"(b[1]));
}
__device__ __forceinline__ void ldsm_x4(uint32_t* r, uint32_t addr) {
    asm volatile("ldmatrix.sync.aligned.m8n8.x4.shared.b16 {%0,%1,%2,%3}, [%4];"
        : "=r"(r[0]), "=r"(r[1]), "=r"(r[2]), "=r"(r[3]) : "r"(addr));
}
__device__ __forceinline__ uint32_t smem_u32(const void* p) {
    uint32_t a;
    asm("{ .reg .u64 t; cvta.to.shared.u64 t, %1; cvt.u32.u64 %0, t; }"
        : "=r"(a) : "l"(p));
    return a;
}
__device__ __forceinline__ void cpa8(uint32_t s, const void* g) {
    asm volatile("cp.async.ca.shared.global [%0], [%1], 8;"
                 :: "r"(s), "l"(g) : "memory");
}
#define CP_COMMIT() asm volatile("cp.async.commit_group;" ::: "memory")
#define CP_WAIT(n)  asm volatile("cp.async.wait_group %0;" :: "n"(n) : "memory")

// ---------------- split-bf16 mma.sync GEMM, single-sync pipeline -------------
#define AST 40
#define TILE_B (128 * AST * 2)
#define STAGE_B (4 * TILE_B)
#define SMEM_GEMM (2 * STAGE_B)   // 81920 B

__global__ __launch_bounds__(256) void mma_gemm(
    int woff,
    const float* __restrict__ biasL, const float* __restrict__ biasR,
    float* __restrict__ Cext, int split,
    int M, int halfN, int K)
{
    extern __shared__ char smem[];
    uint32_t sb = smem_u32(smem);

    int N2 = split ? 2 * halfN : halfN;
    int tid = threadIdx.x, lane = tid & 31, wid = tid >> 5;
    int wm = (wid & 1) * 64, wn = (wid >> 1) * 32;
    int brow = blockIdx.y * 128, bcol = blockIdx.x * 128;

    bool right = split && (bcol >= halfN);
    float* C = split ? (right ? g_xr : g_xl) : Cext;
    const float* bias = right ? biasR : biasL;
    int cbase = bcol - (right ? halfN : 0);

    float c[4][4][4];
    #pragma unroll
    for (int mi = 0; mi < 4; mi++)
        #pragma unroll
        for (int ni = 0; ni < 4; ni++)
            #pragma unroll
            for (int q = 0; q < 4; q++) c[mi][ni][q] = 0.f;

    int lr = tid >> 1;
    int lk = (tid & 1) * 16;
    bool aok = (brow + lr) < M;
    bool bok = (bcol + lr) < N2;
    const __nv_bfloat16* pAh = g_ah + (size_t)(brow + lr) * K + lk;
    const __nv_bfloat16* pAl = g_al + (size_t)(brow + lr) * K + lk;
    const __nv_bfloat16* pBh = g_wh + (size_t)woff + (size_t)(bcol + lr) * K + lk;
    const __nv_bfloat16* pBl = g_wl + (size_t)woff + (size_t)(bcol + lr) * K + lk;
    uint32_t so = (uint32_t)(lr * AST + lk) * 2;

    auto load_stage = [&](int st, int kt) {
        uint32_t s0 = sb + st * STAGE_B + so;
        if (aok) {
            #pragma unroll
            for (int q = 0; q < 4; q++) cpa8(s0 + q * 8, pAh + kt + q * 4);
            #pragma unroll
            for (int q = 0; q < 4; q++) cpa8(s0 + TILE_B + q * 8, pAl + kt + q * 4);
        } else {
            uint2 z = make_uint2(0u, 0u);
            char* d = smem + st * STAGE_B + so;
            #pragma unroll
            for (int q = 0; q < 4; q++) {
                *(uint2*)(d + q * 8) = z;
                *(uint2*)(d + TILE_B + q * 8) = z;
            }
        }
        if (bok) {
            #pragma unroll
            for (int q = 0; q < 4; q++) cpa8(s0 + 2 * TILE_B + q * 8, pBh + kt + q * 4);
            #pragma unroll
            for (int q = 0; q < 4; q++) cpa8(s0 + 3 * TILE_B + q * 8, pBl + kt + q * 4);
        } else {
            uint2 z = make_uint2(0u, 0u);
            char* d = smem + st * STAGE_B + so;
            #pragma unroll
            for (int q = 0; q < 4; q++) {
                *(uint2*)(d + 2 * TILE_B + q * 8) = z;
                *(uint2*)(d + 3 * TILE_B + q * 8) = z;
            }
        }
    };

    int row_a = (lane & 7) + ((lane >> 3) & 1) * 8;
    int col_a = (lane >> 4) * 8;
    uint32_t aoff[4];
    #pragma unroll
    for (int mi = 0; mi < 4; mi++)
        aoff[mi] = (uint32_t)(((wm + mi * 16 + row_a) * AST + col_a) * 2);
    int row_b = ((lane >> 4) * 8) + (lane & 7);
    int col_b = ((lane >> 3) & 1) * 8;
    uint32_t boff[2];
    #pragma unroll
    for (int nh = 0; nh < 2; nh++)
        boff[nh] = (uint32_t)(((wn + nh * 16 + row_b) * AST + col_b) * 2);

    int r = lane >> 2, cc = (lane & 3) * 2;
    int nch = K >> 5;

    load_stage(0, 0);
    CP_COMMIT();

    for (int t = 0; t < nch; t++) {
        CP_WAIT(0);            // stage t resident
        __syncthreads();       // all compute on the other buffer finished
        if (t + 1 < nch) {
            load_stage((t + 1) & 1, (t + 1) << 5);   // overlaps compute below
            CP_COMMIT();
        }

        uint32_t sst = sb + (t & 1) * STAGE_B;
        #pragma unroll
        for (int ks = 0; ks < 2; ks++) {
            uint32_t kbb = (uint32_t)(ks * 32);
            uint32_t ah[4][4], al[4][4], bhv[2][4], blv[2][4];
            #pragma unroll
            for (int mi = 0; mi < 4; mi++) {
                ldsm_x4(ah[mi], sst + aoff[mi] + kbb);
                ldsm_x4(al[mi], sst + TILE_B + aoff[mi] + kbb);
            }
            #pragma unroll
            for (int nh = 0; nh < 2; nh++) {
                ldsm_x4(bhv[nh], sst + 2 * TILE_B + boff[nh] + kbb);
                ldsm_x4(blv[nh], sst + 3 * TILE_B + boff[nh] + kbb);
            }
            #pragma unroll
            for (int mi = 0; mi < 4; mi++)
                #pragma unroll
                for (int ni = 0; ni < 4; ni++) {
                    const uint32_t* bh = &bhv[ni >> 1][(ni & 1) * 2];
                    const uint32_t* bl = &blv[ni >> 1][(ni & 1) * 2];
                    mma16816(c[mi][ni], ah[mi], bh);
                    mma16816(c[mi][ni], ah[mi], bl);
                    mma16816(c[mi][ni], al[mi], bh);
                }
        }
    }

    int r0 = brow + wm + r;
    int c0 = cbase + wn + cc;
    #pragma unroll
    for (int mi = 0; mi < 4; mi++) {
        #pragma unroll
        for (int ni = 0; ni < 4; ni++) {
            int col = c0 + ni * 8;
            if (col >= halfN) continue;
            float bx = bias[col], by = bias[col + 1];
            int row0 = r0 + mi * 16;
            if (row0 < M)
                *(float2*)(C + (size_t)row0 * halfN + col) =
                    make_float2(c[mi][ni][0] + bx, c[mi][ni][1] + by);
            int row1 = row0 + 8;
            if (row1 < M)
                *(float2*)(C + (size_t)row1 * halfN + col) =
                    make_float2(c[mi][ni][2] + bx, c[mi][ni][3] + by);
        }
    }
}

// ---------------- zero counters + dtype detect (merged) -----------------------
// g_is64 statically = 1; detect only clears it. Recomputed before any consumer
// on every replay -> deterministic.
__global__ void zero_detect(const long long* __restrict__ ei) {
    int stride = gridDim.x * blockDim.x;
    for (int i = blockIdx.x * blockDim.x + threadIdx.x; i < NN; i += stride) {
        g_cnt[i] = 0; g_cur[i] = 0;
    }
    bool bad = false;
    for (int i = blockIdx.x * blockDim.x + threadIdx.x; i < NE; i += stride) {
        long long v = ei[i];
        if (v < 0 || v >= NN) bad = true;
    }
    if (bad) g_is64 = 0;
    else if (blockIdx.x == 0 && threadIdx.x == 0) {
        // nothing: keep static value unless proven int32; if a previous replay
        // cleared it and data is int64 it would never be cleared again, but the
        // same buffer re-runs with the same dtype, so the sticky 0 is correct.
    }
}

__device__ __forceinline__ int edge_at(const void* ei, int idx) {
    return g_is64 ? (int)((const long long*)ei)[idx]
                  : ((const int*)ei)[idx];
}

// ---------------- CSR build --------------------------------------------------
__global__ void count_kernel(const void* __restrict__ ei) {
    int e = blockIdx.x * blockDim.x + threadIdx.x;
    if (e >= ET) return;
    int dst = (e < NE) ? edge_at(ei, NE + e) : (e - NE);
    if ((unsigned)dst < NN) atomicAdd(&g_cnt[dst], 1);
}

__global__ void scan_kernel() {
    __shared__ int part[1024];
    int t = threadIdx.x;
    const int CH = (NN + 1023) / 1024;
    int base = t * CH;
    int s = 0;
    for (int k = 0; k < CH; k++) {
        int i = base + k;
        if (i < NN) s += g_cnt[i];
    }
    part[t] = s;
    __syncthreads();
    for (int off = 1; off < 1024; off <<= 1) {
        int v = (t >= off) ? part[t - off] : 0;
        __syncthreads();
        part[t] += v;
        __syncthreads();
    }
    int run = (t == 0) ? 0 : part[t - 1];
    for (int k = 0; k < CH; k++) {
        int i = base + k;
        if (i < NN) { run += g_cnt[i]; g_rowptr[i + 1] = run; }
    }
    if (t == 0) g_rowptr[0] = 0;
}

__global__ void fill_kernel(const void* __restrict__ ei) {
    int e = blockIdx.x * blockDim.x + threadIdx.x;
    if (e >= ET) return;
    int src, dst;
    if (e < NE) { src = edge_at(ei, e); dst = edge_at(ei, NE + e); }
    else        { src = dst = e - NE; }
    if ((unsigned)src >= NN || (unsigned)dst >= NN) return;
    int pos = atomicAdd(&g_cur[dst], 1);
    g_srcs[g_rowptr[dst] + pos] = src;
}

// ---------------- fused GATv2 edge stage + bf16 split epilogue ---------------
__global__ __launch_bounds__(256) void gat_node(
    const float* __restrict__ att, const float* __restrict__ bias, int F)
{
    const float* xl = g_xl;
    const float* xr = g_xr;

    int v = blockIdx.x;
    int start = g_rowptr[v];
    int deg   = g_rowptr[v + 1] - start;
    int F4 = F >> 2;

    extern __shared__ float sh[];
    float* s_xr  = sh;
    float* s_att = sh + F;
    float* s_e   = sh + 2 * F;
    int*   s_src = (int*)(sh + 2 * F + CAP);
    __shared__ float red[32];
    __shared__ float s_bcast;

    int tid = threadIdx.x, bs = blockDim.x;
    int lane = tid & 31, wid = tid >> 5, nw = bs >> 5;

    {
        const float4* xr4  = (const float4*)(xr + (size_t)v * F);
        const float4* att4 = (const float4*)att;
        for (int f = tid; f < F4; f += bs) {
            ((float4*)s_xr)[f]  = xr4[f];
            ((float4*)s_att)[f] = att4[f];
        }
    }
    for (int j = tid; j < deg && j < CAP; j += bs) s_src[j] = g_srcs[start + j];
    __syncthreads();

    for (int j = wid; j < deg; j += nw) {
        int s = (j < CAP) ? s_src[j] : g_srcs[start + j];
        const float4* xl4 = (const float4*)(xl + (size_t)s * F);
        float acc = 0.f;
        #pragma unroll 4
        for (int f = lane; f < F4; f += 32) {
            float4 a = xl4[f];
            float4 r = ((const float4*)s_xr)[f];
            float4 w = ((const float4*)s_att)[f];
            float m;
            m = a.x + r.x; m = (m > 0.f) ? m : m * NEG_SLOPE; acc += m * w.x;
            m = a.y + r.y; m = (m > 0.f) ? m : m * NEG_SLOPE; acc += m * w.y;
            m = a.z + r.z; m = (m > 0.f) ? m : m * NEG_SLOPE; acc += m * w.z;
            m = a.w + r.w; m = (m > 0.f) ? m : m * NEG_SLOPE; acc += m * w.w;
        }
        #pragma unroll
        for (int o = 16; o; o >>= 1) acc += __shfl_down_sync(0xffffffffu, acc, o);
        if (lane == 0) {
            if (j < CAP) s_e[j] = acc;
            else         g_efb[start + j] = acc;
        }
    }
    __syncthreads();

    float mx = -INFINITY;
    for (int j = tid; j < deg; j += bs)
        mx = fmaxf(mx, (j < CAP) ? s_e[j] : g_efb[start + j]);
    #pragma unroll
    for (int o = 16; o; o >>= 1) mx = fmaxf(mx, __shfl_down_sync(0xffffffffu, mx, o));
    if (lane == 0) red[wid] = mx;
    __syncthreads();
    if (wid == 0) {
        float m2 = (lane < nw) ? red[lane] : -INFINITY;
        #pragma unroll
        for (int o = 16; o; o >>= 1) m2 = fmaxf(m2, __shfl_down_sync(0xffffffffu, m2, o));
        if (lane == 0) s_bcast = m2;
    }
    __syncthreads();
    float M = s_bcast;

    float zs = 0.f;
    for (int j = tid; j < deg; j += bs) {
        float e  = (j < CAP) ? s_e[j] : g_efb[start + j];
        float ez = __expf(e - M);
        if (j < CAP) s_e[j] = ez; else g_efb[start + j] = ez;
        zs += ez;
    }
    #pragma unroll
    for (int o = 16; o; o >>= 1) zs += __shfl_down_sync(0xffffffffu, zs, o);
    if (lane == 0) red[wid] = zs;
    __syncthreads();
    if (wid == 0) {
        float z2 = (lane < nw) ? red[lane] : 0.f;
        #pragma unroll
        for (int o = 16; o; o >>= 1) z2 += __shfl_down_sync(0xffffffffu, z2, o);
        if (lane == 0) s_bcast = z2;
    }
    __syncthreads();
    float inv = 1.f / s_bcast;

    const float4* bias4 = (const float4*)bias;
    for (int f = tid; f < F4; f += bs) {
        float4 acc = make_float4(0.f, 0.f, 0.f, 0.f);
        for (int j = 0; j < deg; j++) {
            int s    = (j < CAP) ? s_src[j] : g_srcs[start + j];
            float ez = (j < CAP) ? s_e[j]   : g_efb[start + j];
            float4 xv = ((const float4*)(xl + (size_t)s * F))[f];
            acc.x += ez * xv.x;
            acc.y += ez * xv.y;
            acc.z += ez * xv.z;
            acc.w += ez * xv.w;
        }
        float4 bv = bias4[f];
        float4 o;
        o.x = fmaxf(acc.x * inv + bv.x, 0.f);
        o.y = fmaxf(acc.y * inv + bv.y, 0.f);
        o.z = fmaxf(acc.z * inv + bv.z, 0.f);
        o.w = fmaxf(acc.w * inv + bv.w, 0.f);
        size_t idx = (size_t)v * F + f * 4;
        float lx, ly, lz, lw;
        uint32_t h0 = pack_hi2(o.x, o.y, lx, ly);
        uint32_t h1 = pack_hi2(o.z, o.w, lz, lw);
        *(uint2*)(g_ah + idx) = make_uint2(h0, h1);
        *(uint2*)(g_al + idx) = make_uint2(pack2(lx, ly), pack2(lz, lw));
    }
}

// ---------------- host --------------------------------------------------------
extern "C" void kernel_launch(void* const* d_in, const int* in_sizes, int n_in,
                              void* d_out, int out_size) {
    (void)in_sizes; (void)n_in; (void)out_size;

    const float* x  = (const float*)d_in[0];
    const void*  ei = d_in[1];
    const float *Wl1 = (const float*)d_in[2],  *bl1 = (const float*)d_in[3];
    const float *Wr1 = (const float*)d_in[4],  *br1 = (const float*)d_in[5];
    const float *at1 = (const float*)d_in[6],  *b1  = (const float*)d_in[7];
    const float *Wl2 = (const float*)d_in[8],  *bl2 = (const float*)d_in[9];
    const float *Wr2 = (const float*)d_in[10], *br2 = (const float*)d_in[11];
    const float *at2 = (const float*)d_in[12], *b2  = (const float*)d_in[13];
    const float *Wl3 = (const float*)d_in[14], *bl3 = (const float*)d_in[15];
    const float *Wr3 = (const float*)d_in[16], *br3 = (const float*)d_in[17];
    const float *at3 = (const float*)d_in[18], *b3  = (const float*)d_in[19];
    const float *Wc  = (const float*)d_in[20], *bc  = (const float*)d_in[21];
    float* out = (float*)d_out;

    cudaFuncSetAttribute(mma_gemm,
                         cudaFuncAttributeMaxDynamicSharedMemorySize, SMEM_GEMM);

    // prep: counters+dtype, weight transpose/split, input split, CSR
    zero_detect<<<64, 256>>>((const long long*)ei);
    trans_all<<<dim3(32, 32, 7), 256>>>(Wl1, Wr1, Wl2, Wr2, Wl3, Wr3, Wc);
    conv_split<<<256, 256>>>(x, NN * 128);
    count_kernel<<<(ET + 255) / 256, 256>>>(ei);
    scan_kernel<<<1, 1024>>>();
    fill_kernel<<<(ET + 255) / 256, 256>>>(ei);

    auto gemm2 = [&](int woff, const float* bl, const float* br, int halfN, int K) {
        dim3 grid((2 * halfN + 127) / 128, (NN + 127) / 128);
        mma_gemm<<<grid, 256, SMEM_GEMM>>>(woff, bl, br, nullptr, 1, NN, halfN, K);
    };
    auto gemm1 = [&](int woff, const float* b, float* C, int N, int K) {
        dim3 grid((N + 127) / 128, (NN + 127) / 128);
        mma_gemm<<<grid, 256, SMEM_GEMM>>>(woff, b, b, C, 0, NN, N, K);
    };
    auto gat = [&](const float* ATT, const float* B, int F) {
        size_t shmem = (size_t)(2 * F + CAP) * sizeof(float) + CAP * sizeof(int);
        gat_node<<<NN, 256, shmem>>>(ATT, B, F);
    };

    // layer 1: 128 -> 1024
    gemm2(O1, bl1, br1, 1024, 128);
    gat(at1, b1, 1024);
    // layer 2: 1024 -> 512
    gemm2(O2, bl2, br2, 512, 1024);
    gat(at2, b2, 512);
    // layer 3: 512 -> 128
    gemm2(O3, bl3, br3, 128, 512);
    gat(at3, b3, 128);
    // classifier: 128 -> 64
    gemm1(OC, bc, out, 64, 128);
}